// round 6
// baseline (speedup 1.0000x reference)
#include <cuda_runtime.h>
#include <math.h>

#define E_    2048
#define S_    256
#define Q_    25
#define NN_   36
#define R_    15
#define H_    128
#define K2_   72           // 2*NN_
#define SR_   3840         // S_*R_
#define NPTS  (E_*NN_)     // 73728
#define PPB   64           // points per MLP block
#define MLP_BLOCKS (NPTS/PPB)   // 1152
#define STAGE1_BLOCKS (MLP_BLOCKS + S_)  // 1408
#define GX 30              // N tiles (3840/128)
#define GY 32              // M tiles (2048/64)
#define NPART (GX*GY)      // 960

#define ASTRIDE 68         // 64 + 4 pad (floats)
#define BDSTRIDE 130       // 128 + 2 pad (u64)

typedef unsigned long long u64t;

// ---- scratch ----
__device__ float g_evcat[E_*K2_];          // [E][72]
__device__ u64t  g_AcatT[K2_*SR_];         // [k][sr] duplicated pairs (acc,acc)
__device__ u64t  g_Wdup[2*H_*H_];          // W2,W3 as (w,w) u64, [l][k][j]
__device__ float g_partial[NPART];
__device__ unsigned g_count = 0;

// ---- packed f32x2 helpers ----
__device__ __forceinline__ u64t pk2(float lo, float hi){
    u64t r; asm("mov.b64 %0,{%1,%2};" : "=l"(r) : "f"(lo), "f"(hi)); return r;
}
__device__ __forceinline__ u64t fma2(u64t a, u64t b, u64t c){
    u64t d; asm("fma.rn.f32x2 %0,%1,%2,%3;" : "=l"(d) : "l"(a), "l"(b), "l"(c)); return d;
}
__device__ __forceinline__ void upk2(u64t x, float& lo, float& hi){
    asm("mov.b64 {%0,%1},%2;" : "=f"(lo), "=f"(hi) : "l"(x));
}
union F4U { float4 f; u64t u[2]; };

// fast tanh: 1 - 2/(exp(2x)+1)
__device__ __forceinline__ float fast_tanh(float x){
    float e;
    asm("ex2.approx.f32 %0, %1;" : "=f"(e) : "f"(x * 2.885390081777926f));
    float r;
    asm("rcp.approx.f32 %0, %1;" : "=f"(r) : "f"(e + 1.0f));
    return 1.0f - 2.0f * r;
}

// ============================================================
// Prologue: duplicate W2, W3 into (w,w) u64 pairs.
// ============================================================
__global__ void dup_w(const float* __restrict__ W2, const float* __restrict__ W3){
    int idx = blockIdx.x * blockDim.x + threadIdx.x;   // 0 .. 32767
    if (idx < H_*H_){
        float w = W2[idx];
        g_Wdup[idx] = pk2(w, w);
    } else {
        float w = W3[idx - H_*H_];
        g_Wdup[idx] = pk2(w, w);
    }
}

// ============================================================
// MLP layer on 64 points, 128 threads.
// Per thread: 4 m-pairs (8 m) x 8 n = 32 fma2, m-packed.
// Hout[j][p] = tanh(sum_k Hin[k][p]*W[k][j] + b[j])
// Wd: duplicated (w,w) pairs, [k][j].
// ============================================================
__device__ __forceinline__ void gemm_layer64(const float* __restrict__ Hin, float* __restrict__ Hout,
                                             const u64t* __restrict__ Wd, const float* __restrict__ b){
    const int tid = threadIdx.x;
    const int tx = tid & 15, ty = tid >> 4;   // n0 = tx*8 (128 n), m0 = ty*8 (64 m)
    const int m0 = ty * 8, n0 = tx * 8;

    u64t acc[4][8];
    #pragma unroll
    for (int j = 0; j < 8; j++){
        float bj = __ldg(&b[n0 + j]);
        u64t bb = pk2(bj, bj);
        #pragma unroll
        for (int mp = 0; mp < 4; mp++) acc[mp][j] = bb;
    }

    #pragma unroll 2
    for (int k = 0; k < H_; k++){
        F4U a0, a1;
        a0.f = *(const float4*)(Hin + k*ASTRIDE + m0);
        a1.f = *(const float4*)(Hin + k*ASTRIDE + m0 + 4);
        u64t ap[4] = { a0.u[0], a0.u[1], a1.u[0], a1.u[1] };
        const u64t* wr = Wd + k*H_ + n0;
        ulonglong2 w0 = __ldg((const ulonglong2*)(wr));
        ulonglong2 w1 = __ldg((const ulonglong2*)(wr + 2));
        ulonglong2 w2 = __ldg((const ulonglong2*)(wr + 4));
        ulonglong2 w3 = __ldg((const ulonglong2*)(wr + 6));
        u64t wv[8] = { w0.x, w0.y, w1.x, w1.y, w2.x, w2.y, w3.x, w3.y };
        #pragma unroll
        for (int mp = 0; mp < 4; mp++)
            #pragma unroll
            for (int j = 0; j < 8; j++) acc[mp][j] = fma2(ap[mp], wv[j], acc[mp][j]);
    }

    #pragma unroll
    for (int mp = 0; mp < 4; mp++){
        #pragma unroll
        for (int j = 0; j < 8; j++){
            float lo, hi; upk2(acc[mp][j], lo, hi);
            u64t t = pk2(fast_tanh(lo), fast_tanh(hi));
            *(u64t*)(Hout + (n0 + j)*ASTRIDE + m0 + 2*mp) = t;
        }
    }
}

// ============================================================
// Stage 1: blocks [0,1152) MLP; blocks [1152,1408) build AcatT (dup pairs).
// ============================================================
__global__ __launch_bounds__(128, 3)
void stage1(const float* __restrict__ nodes,
            const float* __restrict__ W1, const float* __restrict__ b1,
            const float* __restrict__ b2, const float* __restrict__ b3,
            const float* __restrict__ W4, const float* __restrict__ b4,
            const float* __restrict__ BDD,
            const float* __restrict__ Ixx, const float* __restrict__ Iyy,
            const float* __restrict__ wq,  const float* __restrict__ Base){
    extern __shared__ float sm[];
    const int tid = threadIdx.x;

    if (blockIdx.x >= MLP_BLOCKS){
        // ---------- build AcatT branch ----------
        const int s = blockIdx.x - MLP_BLOCKS;
        float* WB  = sm;
        float* sI0 = WB  + Q_*R_;
        float* sI1 = sI0 + Q_*NN_;

        for (int i = tid; i < Q_*R_; i += 128){
            int q = i / R_, r = i - q*R_;
            WB[i] = wq[q] * Base[q*R_ + r];
        }
        for (int i = tid; i < Q_*NN_; i += 128){
            sI0[i] = Ixx[s*Q_*NN_ + i];
            sI1[i] = Iyy[s*Q_*NN_ + i];
        }
        __syncthreads();

        for (int idx = tid; idx < R_*K2_; idx += 128){
            int r = idx / K2_, n = idx - r*K2_;
            const float* I = (n < NN_) ? sI0 : sI1;
            int nn = (n < NN_) ? n : (n - NN_);
            float acc = 0.f;
            #pragma unroll
            for (int q = 0; q < Q_; q++) acc += WB[q*R_ + r] * I[q*NN_ + nn];
            g_AcatT[n*SR_ + s*R_ + r] = pk2(acc, acc);
        }
        return;
    }

    // ---------- MLP branch ----------
    float* Ha = sm;                       // [128][ASTRIDE]
    float* Hb = sm + H_*ASTRIDE;
    __shared__ float xs[PPB][2];

    const int p0 = blockIdx.x * PPB;
    ((float*)xs)[tid] = nodes[p0*2 + tid];
    __syncthreads();

    for (int idx = tid; idx < H_*PPB; idx += 128){
        int j = idx >> 6, p = idx & 63;
        float pre = xs[p][0]*__ldg(&W1[j]) + xs[p][1]*__ldg(&W1[H_ + j]) + __ldg(&b1[j]);
        Ha[j*ASTRIDE + p] = fast_tanh(pre);
    }
    __syncthreads();

    gemm_layer64(Ha, Hb, g_Wdup,         b2);  __syncthreads();
    gemm_layer64(Hb, Ha, g_Wdup + H_*H_, b3);  __syncthreads();

    if (tid < PPB){
        float acc = 0.f;
        #pragma unroll 8
        for (int k = 0; k < H_; k++) acc += Ha[k*ASTRIDE + tid] * __ldg(&W4[k]);
        float ev = acc + __ldg(&b4[0]);
        int p = p0 + tid;
        int e = p / NN_, n = p - e*NN_;
        float c00 = __ldg(&BDD[e*4 + 0]), c01 = __ldg(&BDD[e*4 + 1]);
        float c10 = __ldg(&BDD[e*4 + 2]), c11 = __ldg(&BDD[e*4 + 3]);
        g_evcat[e*K2_ + n]       = (c00 + c10) * ev;
        g_evcat[e*K2_ + NN_ + n] = (c01 + c11) * ev;
    }
}

// ============================================================
// Stage 2: 64m x 128n tiles, 128 threads, m-packed 8m x 8n/thread.
// u = -J*(evcat @ Acat^T); fused loss; last-block final reduce.
// ============================================================
__global__ __launch_bounds__(128, 2)
void gemm_loss(const float* __restrict__ J, const float* __restrict__ F,
               float* __restrict__ out){
    extern __shared__ float sm[];
    float* As  = sm;                              // [72][ASTRIDE] floats, m fastest
    u64t*  Bsd = (u64t*)(sm + K2_*ASTRIDE);       // [72][BDSTRIDE] dup pairs, n fastest
    const int tid = threadIdx.x;
    const int m0g = blockIdx.y * 64, n0g = blockIdx.x * 128;

    for (int idx = tid; idx < 64*K2_; idx += 128){
        int m = idx / K2_, k = idx - m*K2_;
        As[k*ASTRIDE + m] = g_evcat[(m0g + m)*K2_ + k];
    }
    for (int idx = tid; idx < K2_*64; idx += 128){
        int k = idx / 64, n2 = (idx - k*64) * 2;
        ulonglong2 v = *(const ulonglong2*)(g_AcatT + k*SR_ + n0g + n2);
        *(ulonglong2*)(Bsd + k*BDSTRIDE + n2) = v;
    }
    __syncthreads();

    const int tx = tid & 15, ty = tid >> 4;   // n0 = tx*8, m0 = ty*8
    const int m0 = ty * 8, n0 = tx * 8;

    u64t acc[4][8];
    #pragma unroll
    for (int mp = 0; mp < 4; mp++)
        #pragma unroll
        for (int j = 0; j < 8; j++) acc[mp][j] = 0ULL;

    #pragma unroll 2
    for (int k = 0; k < K2_; k++){
        F4U a0, a1;
        a0.f = *(const float4*)(As + k*ASTRIDE + m0);
        a1.f = *(const float4*)(As + k*ASTRIDE + m0 + 4);
        u64t ap[4] = { a0.u[0], a0.u[1], a1.u[0], a1.u[1] };
        const u64t* br = Bsd + k*BDSTRIDE + n0;
        ulonglong2 b0 = *(const ulonglong2*)(br);
        ulonglong2 b1 = *(const ulonglong2*)(br + 2);
        ulonglong2 b2 = *(const ulonglong2*)(br + 4);
        ulonglong2 b3 = *(const ulonglong2*)(br + 6);
        u64t bv[8] = { b0.x, b0.y, b1.x, b1.y, b2.x, b2.y, b3.x, b3.y };
        #pragma unroll
        for (int mp = 0; mp < 4; mp++)
            #pragma unroll
            for (int j = 0; j < 8; j++) acc[mp][j] = fma2(ap[mp], bv[j], acc[mp][j]);
    }

    // fused epilogue: rows (e0,e1) per m-pair; res = -J*dot - F; sum res^2
    float lsum = 0.f;
    #pragma unroll
    for (int mp = 0; mp < 4; mp++){
        int e0 = m0g + m0 + 2*mp, e1 = e0 + 1;
        const float* F0 = F + e0*SR_ + n0g + n0;
        const float* F1 = F + e1*SR_ + n0g + n0;
        float4 f00 = __ldg((const float4*)(F0));
        float4 f01 = __ldg((const float4*)(F0 + 4));
        float4 f10 = __ldg((const float4*)(F1));
        float4 f11 = __ldg((const float4*)(F1 + 4));
        float fv0[8] = { f00.x,f00.y,f00.z,f00.w, f01.x,f01.y,f01.z,f01.w };
        float fv1[8] = { f10.x,f10.y,f10.z,f10.w, f11.x,f11.y,f11.z,f11.w };
        #pragma unroll
        for (int j = 0; j < 8; j++){
            float lo, hi; upk2(acc[mp][j], lo, hi);
            int n = n0g + n0 + j;
            int sidx = n / R_;
            float j0 = __ldg(&J[e0*S_ + sidx]);
            float j1 = __ldg(&J[e1*S_ + sidx]);
            float r0 = -j0*lo - fv0[j];
            float r1 = -j1*hi - fv1[j];
            lsum += r0*r0 + r1*r1;
        }
    }

    __shared__ float red[128];
    red[tid] = lsum; __syncthreads();
    #pragma unroll
    for (int s = 64; s > 0; s >>= 1){
        if (tid < s) red[tid] += red[tid + s];
        __syncthreads();
    }

    __shared__ unsigned s_last;
    if (tid == 0){
        g_partial[blockIdx.y * GX + blockIdx.x] = red[0];
        __threadfence();
        unsigned t = atomicAdd(&g_count, 1u);
        s_last = (t == NPART - 1u) ? 1u : 0u;
    }
    __syncthreads();

    if (s_last){
        __shared__ double dred[128];
        double s = 0.0;
        for (int i = tid; i < NPART; i += 128) s += (double)g_partial[i];
        dred[tid] = s; __syncthreads();
        #pragma unroll
        for (int k = 64; k > 0; k >>= 1){
            if (tid < k) dred[tid] += dred[tid + k];
            __syncthreads();
        }
        if (tid == 0){
            out[0] = (float)(dred[0] / (double)R_);
            g_count = 0;
        }
    }
}

// ============================================================
extern "C" void kernel_launch(void* const* d_in, const int* in_sizes, int n_in,
                              void* d_out, int out_size){
    const float* nodes = (const float*)d_in[0];
    const float* W1    = (const float*)d_in[1];
    const float* b1    = (const float*)d_in[2];
    const float* W2    = (const float*)d_in[3];
    const float* b2    = (const float*)d_in[4];
    const float* W3    = (const float*)d_in[5];
    const float* b3    = (const float*)d_in[6];
    const float* W4    = (const float*)d_in[7];
    const float* b4    = (const float*)d_in[8];
    const float* Ixx   = (const float*)d_in[9];
    const float* Iyy   = (const float*)d_in[10];
    const float* BDD   = (const float*)d_in[11];
    const float* wq    = (const float*)d_in[12];
    const float* Base  = (const float*)d_in[13];
    const float* J     = (const float*)d_in[14];
    const float* F     = (const float*)d_in[15];

    const int s1_smem   = 2 * H_ * ASTRIDE * 4;                      // 69632 B
    const int gemm_smem = K2_*ASTRIDE*4 + K2_*BDSTRIDE*8;            // 19584 + 74880 = 94464 B
    cudaFuncSetAttribute(stage1,    cudaFuncAttributeMaxDynamicSharedMemorySize, s1_smem);
    cudaFuncSetAttribute(gemm_loss, cudaFuncAttributeMaxDynamicSharedMemorySize, gemm_smem);

    dup_w<<<2*H_*H_/256, 256>>>(W2, W3);
    stage1<<<STAGE1_BLOCKS, 128, s1_smem>>>(nodes, W1, b1, b2, b3, W4, b4,
                                            BDD, Ixx, Iyy, wq, Base);
    gemm_loss<<<dim3(GX, GY), 128, gemm_smem>>>(J, F, (float*)d_out);
}

// round 7
// speedup vs baseline: 1.0003x; 1.0003x over previous
#include <cuda_runtime.h>
#include <math.h>

#define E_    2048
#define S_    256
#define Q_    25
#define NN_   36
#define R_    15
#define H_    128
#define K2_   72           // 2*NN_
#define SR_   3840         // S_*R_
#define NPTS  (E_*NN_)     // 73728
#define PPB   64           // points per MLP block
#define MLP_BLOCKS (NPTS/PPB)   // 1152
#define STAGE1_BLOCKS (MLP_BLOCKS + S_)  // 1408
#define GX 30              // N tiles (3840/128)
#define GY 32              // M tiles (2048/64)
#define NPART (GX*GY)      // 960

#define ASTRIDE 68         // 64 + 4 pad (floats)
#define BDSTRIDE 130       // 128 + 2 pad (u64)

typedef unsigned long long u64t;

// ---- scratch ----
__device__ float g_evcat[E_*K2_];          // [E][72]
__device__ u64t  g_AcatT[K2_*SR_];         // [k][sr] duplicated pairs (acc,acc)
__device__ u64t  g_Wdup[2*H_*H_];          // W2,W3 as (w,w) u64, [l][k][j]
__device__ float g_partial[NPART];
__device__ unsigned g_count = 0;

// ---- packed f32x2 helpers ----
__device__ __forceinline__ u64t pk2(float lo, float hi){
    u64t r; asm("mov.b64 %0,{%1,%2};" : "=l"(r) : "f"(lo), "f"(hi)); return r;
}
__device__ __forceinline__ u64t fma2(u64t a, u64t b, u64t c){
    u64t d; asm("fma.rn.f32x2 %0,%1,%2,%3;" : "=l"(d) : "l"(a), "l"(b), "l"(c)); return d;
}
__device__ __forceinline__ void upk2(u64t x, float& lo, float& hi){
    asm("mov.b64 {%0,%1},%2;" : "=f"(lo), "=f"(hi) : "l"(x));
}
union F4U { float4 f; u64t u[2]; };

// fast tanh: 1 - 2/(exp(2x)+1)
__device__ __forceinline__ float fast_tanh(float x){
    float e;
    asm("ex2.approx.f32 %0, %1;" : "=f"(e) : "f"(x * 2.885390081777926f));
    float r;
    asm("rcp.approx.f32 %0, %1;" : "=f"(r) : "f"(e + 1.0f));
    return 1.0f - 2.0f * r;
}

// ============================================================
// Prologue: duplicate W2, W3 into (w,w) u64 pairs.
// ============================================================
__global__ void dup_w(const float* __restrict__ W2, const float* __restrict__ W3){
    int idx = blockIdx.x * blockDim.x + threadIdx.x;   // 0 .. 32767
    if (idx < H_*H_){
        float w = W2[idx];
        g_Wdup[idx] = pk2(w, w);
    } else {
        float w = W3[idx - H_*H_];
        g_Wdup[idx] = pk2(w, w);
    }
}

// ============================================================
// MLP layer on 64 points, 128 threads.
// Per thread: 4 m-pairs (8 m) x 8 n = 32 fma2, m-packed.
// Hout[j][p] = tanh(sum_k Hin[k][p]*W[k][j] + b[j])
// Wd: duplicated (w,w) pairs, [k][j].
// ============================================================
__device__ __forceinline__ void gemm_layer64(const float* __restrict__ Hin, float* __restrict__ Hout,
                                             const u64t* __restrict__ Wd, const float* __restrict__ b){
    const int tid = threadIdx.x;
    const int tx = tid & 15, ty = tid >> 4;   // n0 = tx*8 (128 n), m0 = ty*8 (64 m)
    const int m0 = ty * 8, n0 = tx * 8;

    u64t acc[4][8];
    #pragma unroll
    for (int j = 0; j < 8; j++){
        float bj = __ldg(&b[n0 + j]);
        u64t bb = pk2(bj, bj);
        #pragma unroll
        for (int mp = 0; mp < 4; mp++) acc[mp][j] = bb;
    }

    #pragma unroll 2
    for (int k = 0; k < H_; k++){
        F4U a0, a1;
        a0.f = *(const float4*)(Hin + k*ASTRIDE + m0);
        a1.f = *(const float4*)(Hin + k*ASTRIDE + m0 + 4);
        u64t ap[4] = { a0.u[0], a0.u[1], a1.u[0], a1.u[1] };
        const u64t* wr = Wd + k*H_ + n0;
        ulonglong2 w0 = __ldg((const ulonglong2*)(wr));
        ulonglong2 w1 = __ldg((const ulonglong2*)(wr + 2));
        ulonglong2 w2 = __ldg((const ulonglong2*)(wr + 4));
        ulonglong2 w3 = __ldg((const ulonglong2*)(wr + 6));
        u64t wv[8] = { w0.x, w0.y, w1.x, w1.y, w2.x, w2.y, w3.x, w3.y };
        #pragma unroll
        for (int mp = 0; mp < 4; mp++)
            #pragma unroll
            for (int j = 0; j < 8; j++) acc[mp][j] = fma2(ap[mp], wv[j], acc[mp][j]);
    }

    #pragma unroll
    for (int mp = 0; mp < 4; mp++){
        #pragma unroll
        for (int j = 0; j < 8; j++){
            float lo, hi; upk2(acc[mp][j], lo, hi);
            u64t t = pk2(fast_tanh(lo), fast_tanh(hi));
            *(u64t*)(Hout + (n0 + j)*ASTRIDE + m0 + 2*mp) = t;
        }
    }
}

// ============================================================
// Stage 1: blocks [0,1152) MLP; blocks [1152,1408) build AcatT (dup pairs).
// ============================================================
__global__ __launch_bounds__(128, 3)
void stage1(const float* __restrict__ nodes,
            const float* __restrict__ W1, const float* __restrict__ b1,
            const float* __restrict__ b2, const float* __restrict__ b3,
            const float* __restrict__ W4, const float* __restrict__ b4,
            const float* __restrict__ BDD,
            const float* __restrict__ Ixx, const float* __restrict__ Iyy,
            const float* __restrict__ wq,  const float* __restrict__ Base){
    extern __shared__ float sm[];
    const int tid = threadIdx.x;

    if (blockIdx.x >= MLP_BLOCKS){
        // ---------- build AcatT branch ----------
        const int s = blockIdx.x - MLP_BLOCKS;
        float* WB  = sm;
        float* sI0 = WB  + Q_*R_;
        float* sI1 = sI0 + Q_*NN_;

        for (int i = tid; i < Q_*R_; i += 128){
            int q = i / R_, r = i - q*R_;
            WB[i] = wq[q] * Base[q*R_ + r];
        }
        for (int i = tid; i < Q_*NN_; i += 128){
            sI0[i] = Ixx[s*Q_*NN_ + i];
            sI1[i] = Iyy[s*Q_*NN_ + i];
        }
        __syncthreads();

        for (int idx = tid; idx < R_*K2_; idx += 128){
            int r = idx / K2_, n = idx - r*K2_;
            const float* I = (n < NN_) ? sI0 : sI1;
            int nn = (n < NN_) ? n : (n - NN_);
            float acc = 0.f;
            #pragma unroll
            for (int q = 0; q < Q_; q++) acc += WB[q*R_ + r] * I[q*NN_ + nn];
            g_AcatT[n*SR_ + s*R_ + r] = pk2(acc, acc);
        }
        return;
    }

    // ---------- MLP branch ----------
    float* Ha = sm;                       // [128][ASTRIDE]
    float* Hb = sm + H_*ASTRIDE;
    __shared__ float xs[PPB][2];

    const int p0 = blockIdx.x * PPB;
    ((float*)xs)[tid] = nodes[p0*2 + tid];
    __syncthreads();

    for (int idx = tid; idx < H_*PPB; idx += 128){
        int j = idx >> 6, p = idx & 63;
        float pre = xs[p][0]*__ldg(&W1[j]) + xs[p][1]*__ldg(&W1[H_ + j]) + __ldg(&b1[j]);
        Ha[j*ASTRIDE + p] = fast_tanh(pre);
    }
    __syncthreads();

    gemm_layer64(Ha, Hb, g_Wdup,         b2);  __syncthreads();
    gemm_layer64(Hb, Ha, g_Wdup + H_*H_, b3);  __syncthreads();

    if (tid < PPB){
        float acc = 0.f;
        #pragma unroll 8
        for (int k = 0; k < H_; k++) acc += Ha[k*ASTRIDE + tid] * __ldg(&W4[k]);
        float ev = acc + __ldg(&b4[0]);
        int p = p0 + tid;
        int e = p / NN_, n = p - e*NN_;
        float c00 = __ldg(&BDD[e*4 + 0]), c01 = __ldg(&BDD[e*4 + 1]);
        float c10 = __ldg(&BDD[e*4 + 2]), c11 = __ldg(&BDD[e*4 + 3]);
        g_evcat[e*K2_ + n]       = (c00 + c10) * ev;
        g_evcat[e*K2_ + NN_ + n] = (c01 + c11) * ev;
    }
}

// ============================================================
// Stage 2: 64m x 128n tiles, 128 threads, m-packed 8m x 8n/thread.
// u = -J*(evcat @ Acat^T); fused loss; last-block final reduce.
// ============================================================
__global__ __launch_bounds__(128, 2)
void gemm_loss(const float* __restrict__ J, const float* __restrict__ F,
               float* __restrict__ out){
    extern __shared__ float sm[];
    float* As  = sm;                              // [72][ASTRIDE] floats, m fastest
    u64t*  Bsd = (u64t*)(sm + K2_*ASTRIDE);       // [72][BDSTRIDE] dup pairs, n fastest
    const int tid = threadIdx.x;
    const int m0g = blockIdx.y * 64, n0g = blockIdx.x * 128;

    for (int idx = tid; idx < 64*K2_; idx += 128){
        int m = idx / K2_, k = idx - m*K2_;
        As[k*ASTRIDE + m] = g_evcat[(m0g + m)*K2_ + k];
    }
    for (int idx = tid; idx < K2_*64; idx += 128){
        int k = idx / 64, n2 = (idx - k*64) * 2;
        ulonglong2 v = *(const ulonglong2*)(g_AcatT + k*SR_ + n0g + n2);
        *(ulonglong2*)(Bsd + k*BDSTRIDE + n2) = v;
    }
    __syncthreads();

    const int tx = tid & 15, ty = tid >> 4;   // n0 = tx*8, m0 = ty*8
    const int m0 = ty * 8, n0 = tx * 8;

    u64t acc[4][8];
    #pragma unroll
    for (int mp = 0; mp < 4; mp++)
        #pragma unroll
        for (int j = 0; j < 8; j++) acc[mp][j] = 0ULL;

    #pragma unroll 2
    for (int k = 0; k < K2_; k++){
        F4U a0, a1;
        a0.f = *(const float4*)(As + k*ASTRIDE + m0);
        a1.f = *(const float4*)(As + k*ASTRIDE + m0 + 4);
        u64t ap[4] = { a0.u[0], a0.u[1], a1.u[0], a1.u[1] };
        const u64t* br = Bsd + k*BDSTRIDE + n0;
        ulonglong2 b0 = *(const ulonglong2*)(br);
        ulonglong2 b1 = *(const ulonglong2*)(br + 2);
        ulonglong2 b2 = *(const ulonglong2*)(br + 4);
        ulonglong2 b3 = *(const ulonglong2*)(br + 6);
        u64t bv[8] = { b0.x, b0.y, b1.x, b1.y, b2.x, b2.y, b3.x, b3.y };
        #pragma unroll
        for (int mp = 0; mp < 4; mp++)
            #pragma unroll
            for (int j = 0; j < 8; j++) acc[mp][j] = fma2(ap[mp], bv[j], acc[mp][j]);
    }

    // fused epilogue: rows (e0,e1) per m-pair; res = -J*dot - F; sum res^2
    float lsum = 0.f;
    #pragma unroll
    for (int mp = 0; mp < 4; mp++){
        int e0 = m0g + m0 + 2*mp, e1 = e0 + 1;
        const float* F0 = F + e0*SR_ + n0g + n0;
        const float* F1 = F + e1*SR_ + n0g + n0;
        float4 f00 = __ldg((const float4*)(F0));
        float4 f01 = __ldg((const float4*)(F0 + 4));
        float4 f10 = __ldg((const float4*)(F1));
        float4 f11 = __ldg((const float4*)(F1 + 4));
        float fv0[8] = { f00.x,f00.y,f00.z,f00.w, f01.x,f01.y,f01.z,f01.w };
        float fv1[8] = { f10.x,f10.y,f10.z,f10.w, f11.x,f11.y,f11.z,f11.w };
        #pragma unroll
        for (int j = 0; j < 8; j++){
            float lo, hi; upk2(acc[mp][j], lo, hi);
            int n = n0g + n0 + j;
            int sidx = n / R_;
            float j0 = __ldg(&J[e0*S_ + sidx]);
            float j1 = __ldg(&J[e1*S_ + sidx]);
            float r0 = -j0*lo - fv0[j];
            float r1 = -j1*hi - fv1[j];
            lsum += r0*r0 + r1*r1;
        }
    }

    __shared__ float red[128];
    red[tid] = lsum; __syncthreads();
    #pragma unroll
    for (int s = 64; s > 0; s >>= 1){
        if (tid < s) red[tid] += red[tid + s];
        __syncthreads();
    }

    __shared__ unsigned s_last;
    if (tid == 0){
        g_partial[blockIdx.y * GX + blockIdx.x] = red[0];
        __threadfence();
        unsigned t = atomicAdd(&g_count, 1u);
        s_last = (t == NPART - 1u) ? 1u : 0u;
    }
    __syncthreads();

    if (s_last){
        __shared__ double dred[128];
        double s = 0.0;
        for (int i = tid; i < NPART; i += 128) s += (double)g_partial[i];
        dred[tid] = s; __syncthreads();
        #pragma unroll
        for (int k = 64; k > 0; k >>= 1){
            if (tid < k) dred[tid] += dred[tid + k];
            __syncthreads();
        }
        if (tid == 0){
            out[0] = (float)(dred[0] / (double)R_);
            g_count = 0;
        }
    }
}

// ============================================================
extern "C" void kernel_launch(void* const* d_in, const int* in_sizes, int n_in,
                              void* d_out, int out_size){
    const float* nodes = (const float*)d_in[0];
    const float* W1    = (const float*)d_in[1];
    const float* b1    = (const float*)d_in[2];
    const float* W2    = (const float*)d_in[3];
    const float* b2    = (const float*)d_in[4];
    const float* W3    = (const float*)d_in[5];
    const float* b3    = (const float*)d_in[6];
    const float* W4    = (const float*)d_in[7];
    const float* b4    = (const float*)d_in[8];
    const float* Ixx   = (const float*)d_in[9];
    const float* Iyy   = (const float*)d_in[10];
    const float* BDD   = (const float*)d_in[11];
    const float* wq    = (const float*)d_in[12];
    const float* Base  = (const float*)d_in[13];
    const float* J     = (const float*)d_in[14];
    const float* F     = (const float*)d_in[15];

    const int s1_smem   = 2 * H_ * ASTRIDE * 4;                      // 69632 B
    const int gemm_smem = K2_*ASTRIDE*4 + K2_*BDSTRIDE*8;            // 19584 + 74880 = 94464 B
    cudaFuncSetAttribute(stage1,    cudaFuncAttributeMaxDynamicSharedMemorySize, s1_smem);
    cudaFuncSetAttribute(gemm_loss, cudaFuncAttributeMaxDynamicSharedMemorySize, gemm_smem);

    dup_w<<<2*H_*H_/256, 256>>>(W2, W3);
    stage1<<<STAGE1_BLOCKS, 128, s1_smem>>>(nodes, W1, b1, b2, b3, W4, b4,
                                            BDD, Ixx, Iyy, wq, Base);
    gemm_loss<<<dim3(GX, GY), 128, gemm_smem>>>(J, F, (float*)d_out);
}

// round 9
// speedup vs baseline: 3.9949x; 3.9936x over previous
#include <cuda_runtime.h>
#include <stdint.h>
#include <math.h>

#define E_    2048
#define S_    256
#define Q_    25
#define NN_   36
#define R_    15
#define H_    128
#define K2_   72
#define SR_   3840
#define NPTS  (E_*NN_)          // 73728
#define MLP_BLOCKS (NPTS/128)   // 576
#define STAGE1_BLOCKS (S_ + MLP_BLOCKS)  // acat first: 256 + 576
#define GX 30
#define GY 32
#define NPART (GX*GY)
#define ASTRIDE 68
#define BSTRIDE 132
#define WS 132                  // smem stride (u32 words) for W and A tiles in MLP

// ---- scratch ----
__device__ float    g_evcat[E_*K2_];
__device__ float    g_Acat[SR_*K2_];
__device__ float    g_partial[NPART];
__device__ unsigned g_count = 0;

// ---- f32x2 helpers (gemm_loss) ----
typedef unsigned long long u64t;
__device__ __forceinline__ u64t pk2(float lo, float hi){
    u64t r; asm("mov.b64 %0,{%1,%2};" : "=l"(r) : "f"(lo), "f"(hi)); return r;
}
__device__ __forceinline__ u64t fma2(u64t a, u64t b, u64t c){
    u64t d; asm("fma.rn.f32x2 %0,%1,%2,%3;" : "=l"(d) : "l"(a), "l"(b), "l"(c)); return d;
}
__device__ __forceinline__ void upk2(u64t x, float& lo, float& hi){
    asm("mov.b64 {%0,%1},%2;" : "=f"(lo), "=f"(hi) : "l"(x));
}
union F4U { float4 f; u64t u[2]; };

__device__ __forceinline__ float fast_tanh(float x){
    float e;
    asm("ex2.approx.f32 %0, %1;" : "=f"(e) : "f"(x * 2.885390081777926f));
    float r;
    asm("rcp.approx.f32 %0, %1;" : "=f"(r) : "f"(e + 1.0f));
    return 1.0f - 2.0f * r;
}
__device__ __forceinline__ uint32_t to_tf32(float x){
    uint32_t v; asm("cvt.rna.tf32.f32 %0, %1;" : "=r"(v) : "f"(x)); return v;
}

// warp-level tf32 MMA: D(16x8) += A(16x8,row) * B(8x8,col)
__device__ __forceinline__ void wmma8(float* c, const uint32_t* a, const uint32_t* b){
    asm volatile("mma.sync.aligned.m16n8k8.row.col.f32.tf32.tf32.f32 "
        "{%0,%1,%2,%3},{%4,%5,%6,%7},{%8,%9},{%0,%1,%2,%3};"
        : "+f"(c[0]), "+f"(c[1]), "+f"(c[2]), "+f"(c[3])
        : "r"(a[0]), "r"(a[1]), "r"(a[2]), "r"(a[3]), "r"(b[0]), "r"(b[1]));
}

// ============================================================
// One MLP layer via mma.sync: A[128m x 128k](tf32, smem) @ W[128k x 128n](tf32)
// -> tanh(. + bias) -> overwrite A in place (tf32 or raw fp32).
// 8 warps: warp w does rows (w&3)*32..+31, cols (w>>2)*64..+63.
// ============================================================
__device__ __forceinline__ void mma_layer(uint32_t* __restrict__ A,
                                          const uint32_t* __restrict__ W,
                                          const float* __restrict__ bias,
                                          int l, int mrow, int ncol, int out_tf32){
    float c[2][8][4];
    #pragma unroll
    for (int mt = 0; mt < 2; mt++)
        #pragma unroll
        for (int nt = 0; nt < 8; nt++)
            #pragma unroll
            for (int i = 0; i < 4; i++) c[mt][nt][i] = 0.f;

    const int lg = l >> 2, lt = l & 3;

    #pragma unroll 2
    for (int kk = 0; kk < 16; kk++){
        const int k0 = kk * 8;
        uint32_t a[2][4];
        #pragma unroll
        for (int mt = 0; mt < 2; mt++){
            const int r = mrow + mt*16 + lg;
            a[mt][0] = A[ r     *WS + k0     + lt];
            a[mt][2] = A[ r     *WS + k0 + 4 + lt];
            a[mt][1] = A[(r + 8)*WS + k0     + lt];
            a[mt][3] = A[(r + 8)*WS + k0 + 4 + lt];
        }
        #pragma unroll
        for (int nt = 0; nt < 8; nt++){
            uint32_t b[2];
            const int n = ncol + nt*8 + lg;
            b[0] = W[(k0     + lt)*WS + n];
            b[1] = W[(k0 + 4 + lt)*WS + n];
            wmma8(c[0][nt], a[0], b);
            wmma8(c[1][nt], a[1], b);
        }
    }
    __syncthreads();   // all reads of A done before overwrite

    #pragma unroll
    for (int mt = 0; mt < 2; mt++){
        const int r = mrow + mt*16 + lg;
        #pragma unroll
        for (int nt = 0; nt < 8; nt++){
            const int n = ncol + nt*8 + 2*lt;
            const float b0 = bias[n], b1 = bias[n+1];
            float v0 = fast_tanh(c[mt][nt][0] + b0);
            float v1 = fast_tanh(c[mt][nt][1] + b1);
            float v2 = fast_tanh(c[mt][nt][2] + b0);
            float v3 = fast_tanh(c[mt][nt][3] + b1);
            uint32_t u0, u1, u2, u3;
            if (out_tf32){
                u0 = to_tf32(v0); u1 = to_tf32(v1); u2 = to_tf32(v2); u3 = to_tf32(v3);
            } else {
                u0 = __float_as_uint(v0); u1 = __float_as_uint(v1);
                u2 = __float_as_uint(v2); u3 = __float_as_uint(v3);
            }
            *(u64t*)(A +  r     *WS + n) = pk2(__uint_as_float(u0), __uint_as_float(u1));
            *(u64t*)(A + (r + 8)*WS + n) = pk2(__uint_as_float(u2), __uint_as_float(u3));
        }
    }
    __syncthreads();
}

// ============================================================
// Stage 1: blocks [0,256) build Acat; blocks [256,832) = MLP (128 pts each).
// ============================================================
__global__ __launch_bounds__(256, 1)
void stage1(const float* __restrict__ nodes,
            const float* __restrict__ W1, const float* __restrict__ b1,
            const float* __restrict__ W2, const float* __restrict__ b2,
            const float* __restrict__ W3, const float* __restrict__ b3,
            const float* __restrict__ W4, const float* __restrict__ b4,
            const float* __restrict__ BDD,
            const float* __restrict__ Ixx, const float* __restrict__ Iyy,
            const float* __restrict__ wq,  const float* __restrict__ Base){
    extern __shared__ __align__(16) uint32_t smw[];
    const int tid = threadIdx.x;

    if (blockIdx.x < S_){
        // ---------- build Acat ----------
        const int s = blockIdx.x;
        float* WB  = (float*)smw;
        float* sI0 = WB  + Q_*R_;
        float* sI1 = sI0 + Q_*NN_;
        for (int i = tid; i < Q_*R_; i += 256){
            int q = i / R_, r = i - q*R_;
            WB[i] = wq[q] * Base[q*R_ + r];
        }
        for (int i = tid; i < Q_*NN_; i += 256){
            sI0[i] = Ixx[s*Q_*NN_ + i];
            sI1[i] = Iyy[s*Q_*NN_ + i];
        }
        __syncthreads();
        for (int idx = tid; idx < R_*K2_; idx += 256){
            int r = idx / K2_, n = idx - r*K2_;
            const float* I = (n < NN_) ? sI0 : sI1;
            int nn = (n < NN_) ? n : (n - NN_);
            float acc = 0.f;
            #pragma unroll
            for (int q = 0; q < Q_; q++) acc += WB[q*R_ + r] * I[q*NN_ + nn];
            g_Acat[(s*R_ + r)*K2_ + n] = acc;
        }
        return;
    }

    // ---------- MLP on 128 points ----------
    uint32_t* W2s = smw;                  // [128][WS] tf32
    uint32_t* W3s = smw + H_*WS;          // [128][WS] tf32
    uint32_t* A   = smw + 2*H_*WS;        // [128][WS] activations
    __shared__ float sW1[2*H_], sB1[H_], sB2[H_], sB3[H_], sW4[H_+1];

    const int mb = blockIdx.x - S_;
    const int p0 = mb * 128;
    const int w  = tid >> 5, l = tid & 31;
    const int mrow = (w & 3) * 32, ncol = (w >> 2) * 64;

    // load weights -> tf32 smem (padded stride)
    for (int i = tid; i < H_*H_; i += 256){
        int k = i >> 7, n = i & 127;
        W2s[k*WS + n] = to_tf32(W2[i]);
        W3s[k*WS + n] = to_tf32(W3[i]);
    }
    if (tid < 2*H_) sW1[tid] = W1[tid];
    if (tid < H_){ sB1[tid] = b1[tid]; sB2[tid] = b2[tid]; sB3[tid] = b3[tid]; sW4[tid] = W4[tid]; }
    if (tid == 0) sW4[H_] = b4[0];
    __syncthreads();

    // layer 1: thread t -> point p = t/2, cols half (t&1)*64
    {
        const int p  = tid >> 1;
        const int jh = (tid & 1) * 64;
        float2 xy = ((const float2*)nodes)[p0 + p];
        #pragma unroll 8
        for (int j = jh; j < jh + 64; j += 2){
            float v0 = fast_tanh(fmaf(xy.x, sW1[j  ], fmaf(xy.y, sW1[H_+j  ], sB1[j  ])));
            float v1 = fast_tanh(fmaf(xy.x, sW1[j+1], fmaf(xy.y, sW1[H_+j+1], sB1[j+1])));
            *(u64t*)(A + p*WS + j) =
                pk2(__uint_as_float(to_tf32(v0)), __uint_as_float(to_tf32(v1)));
        }
    }
    __syncthreads();

    mma_layer(A, W2s, sB2, l, mrow, ncol, 1);   // h2 (tf32)
    mma_layer(A, W3s, sB3, l, mrow, ncol, 0);   // h3 (fp32)

    // layer 4: 128 threads, one point each
    if (tid < 128){
        const float* Af = (const float*)(A + tid*WS);
        float acc = 0.f;
        #pragma unroll 8
        for (int k = 0; k < H_; k++) acc = fmaf(Af[k], sW4[k], acc);
        float ev = acc + sW4[H_];
        int p = p0 + tid;
        int e = p / NN_, n = p - e*NN_;
        float c00 = __ldg(&BDD[e*4 + 0]), c01 = __ldg(&BDD[e*4 + 1]);
        float c10 = __ldg(&BDD[e*4 + 2]), c11 = __ldg(&BDD[e*4 + 3]);
        g_evcat[e*K2_ + n]       = (c00 + c10) * ev;
        g_evcat[e*K2_ + NN_ + n] = (c01 + c11) * ev;
    }
}

// ============================================================
// Stage 2 (R3-proven): 64m x 128n tiles, 128 threads, 8x8 n-packed f32x2.
// ============================================================
__global__ __launch_bounds__(128, 3)
void gemm_loss(const float* __restrict__ J, const float* __restrict__ F,
               float* __restrict__ out){
    extern __shared__ float sm[];
    float* As = sm;                    // [72][ASTRIDE]
    float* Bs = sm + K2_*ASTRIDE;      // [72][BSTRIDE]
    const int tid = threadIdx.x;
    const int m0g = blockIdx.y * 64, n0g = blockIdx.x * 128;

    for (int idx = tid; idx < 64*K2_; idx += 128){
        int m = idx / K2_, k = idx - m*K2_;
        As[k*ASTRIDE + m] = g_evcat[(m0g + m)*K2_ + k];
    }
    for (int idx = tid; idx < 128*K2_; idx += 128){
        int n = idx / K2_, k = idx - n*K2_;
        Bs[k*BSTRIDE + n] = g_Acat[(n0g + n)*K2_ + k];
    }
    __syncthreads();

    const int tx = tid & 15, ty = tid >> 4;
    const int m0 = ty * 8, n0 = tx * 8;

    u64t acc[8][4];
    #pragma unroll
    for (int i = 0; i < 8; i++)
        #pragma unroll
        for (int jp = 0; jp < 4; jp++) acc[i][jp] = 0ULL;

    #pragma unroll 4
    for (int k = 0; k < K2_; k++){
        float4 a0 = *(const float4*)(As + k*ASTRIDE + m0);
        float4 a1 = *(const float4*)(As + k*ASTRIDE + m0 + 4);
        F4U b0, b1;
        b0.f = *(const float4*)(Bs + k*BSTRIDE + n0);
        b1.f = *(const float4*)(Bs + k*BSTRIDE + n0 + 4);
        u64t bv[4] = { b0.u[0], b0.u[1], b1.u[0], b1.u[1] };
        float av[8] = { a0.x, a0.y, a0.z, a0.w, a1.x, a1.y, a1.z, a1.w };
        #pragma unroll
        for (int i = 0; i < 8; i++){
            u64t ad = pk2(av[i], av[i]);
            #pragma unroll
            for (int jp = 0; jp < 4; jp++) acc[i][jp] = fma2(ad, bv[jp], acc[i][jp]);
        }
    }

    float lsum = 0.f;
    #pragma unroll
    for (int i = 0; i < 8; i++){
        int e = m0g + m0 + i;
        const float* Fr = F + e*SR_ + n0g + n0;
        const float* Jr = J + e*S_;
        float4 f0 = __ldg((const float4*)(Fr));
        float4 f1 = __ldg((const float4*)(Fr + 4));
        float fv[8] = { f0.x,f0.y,f0.z,f0.w, f1.x,f1.y,f1.z,f1.w };
        #pragma unroll
        for (int jp = 0; jp < 4; jp++){
            float lo, hi; upk2(acc[i][jp], lo, hi);
            int n = n0g + n0 + 2*jp;
            float j0 = __ldg(&Jr[(n    ) / R_]);
            float j1 = __ldg(&Jr[(n + 1) / R_]);
            float r0 = -j0*lo - fv[2*jp];
            float r1 = -j1*hi - fv[2*jp + 1];
            lsum += r0*r0 + r1*r1;
        }
    }

    __shared__ float red[128];
    red[tid] = lsum; __syncthreads();
    #pragma unroll
    for (int s = 64; s > 0; s >>= 1){
        if (tid < s) red[tid] += red[tid + s];
        __syncthreads();
    }

    __shared__ unsigned s_last;
    if (tid == 0){
        g_partial[blockIdx.y * GX + blockIdx.x] = red[0];
        __threadfence();
        unsigned t = atomicAdd(&g_count, 1u);
        s_last = (t == NPART - 1u) ? 1u : 0u;
    }
    __syncthreads();

    if (s_last){
        __shared__ double dred[128];
        double s = 0.0;
        for (int i = tid; i < NPART; i += 128) s += (double)g_partial[i];
        dred[tid] = s; __syncthreads();
        #pragma unroll
        for (int k = 64; k > 0; k >>= 1){
            if (tid < k) dred[tid] += dred[tid + k];
            __syncthreads();
        }
        if (tid == 0){
            out[0] = (float)(dred[0] / (double)R_);
            g_count = 0;
        }
    }
}

// ============================================================
extern "C" void kernel_launch(void* const* d_in, const int* in_sizes, int n_in,
                              void* d_out, int out_size){
    const float* nodes = (const float*)d_in[0];
    const float* W1    = (const float*)d_in[1];
    const float* b1    = (const float*)d_in[2];
    const float* W2    = (const float*)d_in[3];
    const float* b2    = (const float*)d_in[4];
    const float* W3    = (const float*)d_in[5];
    const float* b3    = (const float*)d_in[6];
    const float* W4    = (const float*)d_in[7];
    const float* b4    = (const float*)d_in[8];
    const float* Ixx   = (const float*)d_in[9];
    const float* Iyy   = (const float*)d_in[10];
    const float* BDD   = (const float*)d_in[11];
    const float* wq    = (const float*)d_in[12];
    const float* Base  = (const float*)d_in[13];
    const float* J     = (const float*)d_in[14];
    const float* F     = (const float*)d_in[15];

    const int s1_smem   = 3 * H_ * WS * 4;                    // 202752 B
    const int gemm_smem = (K2_*ASTRIDE + K2_*BSTRIDE) * 4;    // 57600 B
    cudaFuncSetAttribute(stage1,    cudaFuncAttributeMaxDynamicSharedMemorySize, s1_smem);
    cudaFuncSetAttribute(gemm_loss, cudaFuncAttributeMaxDynamicSharedMemorySize, gemm_smem);

    stage1<<<STAGE1_BLOCKS, 256, s1_smem>>>(nodes, W1, b1, W2, b2, W3, b3, W4, b4,
                                            BDD, Ixx, Iyy, wq, Base);
    gemm_loss<<<dim3(GX, GY), 128, gemm_smem>>>(J, F, (float*)d_out);
}

// round 10
// speedup vs baseline: 5.1527x; 1.2898x over previous
#include <cuda_runtime.h>
#include <stdint.h>
#include <math.h>

#define E_    2048
#define S_    256
#define Q_    25
#define NN_   36
#define R_    15
#define H_    128
#define K2_   72
#define SR_   3840
#define NPTS  (E_*NN_)          // 73728
#define TPB   4                 // tiles (of 128 pts) per MLP block
#define MLP_BLOCKS (NPTS/(128*TPB))      // 144
#define STAGE1_BLOCKS (MLP_BLOCKS + S_)  // MLP first: 144 + 256
#define GX 30                   // N tiles (3840/128)
#define GY 16                   // M tiles (2048/128)
#define NPART (GX*GY)           // 480
#define WS 132                  // smem word stride, MLP tiles
#define AK 76                   // gemm_loss A tile k-stride (72+4)
#define BN 132                  // gemm_loss B tile n-stride

// ---- scratch ----
__device__ float    g_evcat[E_*K2_];
__device__ float    g_Acat[SR_*K2_];
__device__ float    g_partial[NPART];
__device__ unsigned g_count = 0;

typedef unsigned long long u64t;
__device__ __forceinline__ u64t pk2(float lo, float hi){
    u64t r; asm("mov.b64 %0,{%1,%2};" : "=l"(r) : "f"(lo), "f"(hi)); return r;
}
__device__ __forceinline__ float fast_tanh(float x){
    float e;
    asm("ex2.approx.f32 %0, %1;" : "=f"(e) : "f"(x * 2.885390081777926f));
    float r;
    asm("rcp.approx.f32 %0, %1;" : "=f"(r) : "f"(e + 1.0f));
    return 1.0f - 2.0f * r;
}
__device__ __forceinline__ uint32_t to_tf32(float x){
    uint32_t v; asm("cvt.rna.tf32.f32 %0, %1;" : "=r"(v) : "f"(x)); return v;
}

// warp-level tf32 MMA: D(16x8) += A(16x8,row) * B(8x8,col)
__device__ __forceinline__ void wmma8(float* c, const uint32_t* a, const uint32_t* b){
    asm volatile("mma.sync.aligned.m16n8k8.row.col.f32.tf32.tf32.f32 "
        "{%0,%1,%2,%3},{%4,%5,%6,%7},{%8,%9},{%0,%1,%2,%3};"
        : "+f"(c[0]), "+f"(c[1]), "+f"(c[2]), "+f"(c[3])
        : "r"(a[0]), "r"(a[1]), "r"(a[2]), "r"(a[3]), "r"(b[0]), "r"(b[1]));
}

// ============================================================
// One MLP layer via mma.sync (layout proven in R9).
// ============================================================
__device__ __forceinline__ void mma_layer(uint32_t* __restrict__ A,
                                          const uint32_t* __restrict__ W,
                                          const float* __restrict__ bias,
                                          int l, int mrow, int ncol, int out_tf32){
    float c[2][8][4];
    #pragma unroll
    for (int mt = 0; mt < 2; mt++)
        #pragma unroll
        for (int nt = 0; nt < 8; nt++)
            #pragma unroll
            for (int i = 0; i < 4; i++) c[mt][nt][i] = 0.f;

    const int lg = l >> 2, lt = l & 3;

    #pragma unroll 2
    for (int kk = 0; kk < 16; kk++){
        const int k0 = kk * 8;
        uint32_t a[2][4];
        #pragma unroll
        for (int mt = 0; mt < 2; mt++){
            const int r = mrow + mt*16 + lg;
            a[mt][0] = A[ r     *WS + k0     + lt];
            a[mt][2] = A[ r     *WS + k0 + 4 + lt];
            a[mt][1] = A[(r + 8)*WS + k0     + lt];
            a[mt][3] = A[(r + 8)*WS + k0 + 4 + lt];
        }
        #pragma unroll
        for (int nt = 0; nt < 8; nt++){
            uint32_t b[2];
            const int n = ncol + nt*8 + lg;
            b[0] = W[(k0     + lt)*WS + n];
            b[1] = W[(k0 + 4 + lt)*WS + n];
            wmma8(c[0][nt], a[0], b);
            wmma8(c[1][nt], a[1], b);
        }
    }
    __syncthreads();

    #pragma unroll
    for (int mt = 0; mt < 2; mt++){
        const int r = mrow + mt*16 + lg;
        #pragma unroll
        for (int nt = 0; nt < 8; nt++){
            const int n = ncol + nt*8 + 2*lt;
            const float b0 = bias[n], b1 = bias[n+1];
            float v0 = fast_tanh(c[mt][nt][0] + b0);
            float v1 = fast_tanh(c[mt][nt][1] + b1);
            float v2 = fast_tanh(c[mt][nt][2] + b0);
            float v3 = fast_tanh(c[mt][nt][3] + b1);
            uint32_t u0, u1, u2, u3;
            if (out_tf32){
                u0 = to_tf32(v0); u1 = to_tf32(v1); u2 = to_tf32(v2); u3 = to_tf32(v3);
            } else {
                u0 = __float_as_uint(v0); u1 = __float_as_uint(v1);
                u2 = __float_as_uint(v2); u3 = __float_as_uint(v3);
            }
            *(u64t*)(A +  r     *WS + n) = pk2(__uint_as_float(u0), __uint_as_float(u1));
            *(u64t*)(A + (r + 8)*WS + n) = pk2(__uint_as_float(u2), __uint_as_float(u3));
        }
    }
    __syncthreads();
}

// ============================================================
// Stage 1: blocks [0,144) MLP (4 tiles of 128 pts, weights loaded once);
//          blocks [144,400) build Acat.
// ============================================================
__global__ __launch_bounds__(256, 1)
void stage1(const float* __restrict__ nodes,
            const float* __restrict__ W1, const float* __restrict__ b1,
            const float* __restrict__ W2, const float* __restrict__ b2,
            const float* __restrict__ W3, const float* __restrict__ b3,
            const float* __restrict__ W4, const float* __restrict__ b4,
            const float* __restrict__ BDD,
            const float* __restrict__ Ixx, const float* __restrict__ Iyy,
            const float* __restrict__ wq,  const float* __restrict__ Base){
    extern __shared__ __align__(16) uint32_t smw[];
    const int tid = threadIdx.x;

    if (blockIdx.x >= MLP_BLOCKS){
        // ---------- build Acat ----------
        const int s = blockIdx.x - MLP_BLOCKS;
        float* WB  = (float*)smw;
        float* sI0 = WB  + Q_*R_;
        float* sI1 = sI0 + Q_*NN_;
        for (int i = tid; i < Q_*R_; i += 256){
            int q = i / R_, r = i - q*R_;
            WB[i] = wq[q] * Base[q*R_ + r];
        }
        for (int i = tid; i < Q_*NN_; i += 256){
            sI0[i] = Ixx[s*Q_*NN_ + i];
            sI1[i] = Iyy[s*Q_*NN_ + i];
        }
        __syncthreads();
        for (int idx = tid; idx < R_*K2_; idx += 256){
            int r = idx / K2_, n = idx - r*K2_;
            const float* I = (n < NN_) ? sI0 : sI1;
            int nn = (n < NN_) ? n : (n - NN_);
            float acc = 0.f;
            #pragma unroll
            for (int q = 0; q < Q_; q++) acc += WB[q*R_ + r] * I[q*NN_ + nn];
            g_Acat[(s*R_ + r)*K2_ + n] = acc;
        }
        return;
    }

    // ---------- MLP: 4 tiles of 128 points ----------
    uint32_t* W2s = smw;                  // [128][WS] tf32
    uint32_t* W3s = smw + H_*WS;
    uint32_t* A   = smw + 2*H_*WS;        // [128][WS]
    __shared__ float sW1[2*H_], sB1[H_], sB2[H_], sB3[H_], sW4[H_+1];

    const int w  = tid >> 5, l = tid & 31;
    const int mrow = (w & 3) * 32, ncol = (w >> 2) * 64;

    for (int i = tid; i < H_*H_; i += 256){
        int k = i >> 7, n = i & 127;
        W2s[k*WS + n] = to_tf32(W2[i]);
        W3s[k*WS + n] = to_tf32(W3[i]);
    }
    if (tid < 2*H_) sW1[tid] = W1[tid];
    if (tid < H_){ sB1[tid] = b1[tid]; sB2[tid] = b2[tid]; sB3[tid] = b3[tid]; sW4[tid] = W4[tid]; }
    if (tid == 0) sW4[H_] = b4[0];
    __syncthreads();

    for (int t = 0; t < TPB; t++){
        const int p0 = (blockIdx.x * TPB + t) * 128;

        // layer 1: thread -> point tid/2, half of hidden units
        {
            const int p  = tid >> 1;
            const int jh = (tid & 1) * 64;
            float2 xy = ((const float2*)nodes)[p0 + p];
            #pragma unroll 8
            for (int j = jh; j < jh + 64; j += 2){
                float v0 = fast_tanh(fmaf(xy.x, sW1[j  ], fmaf(xy.y, sW1[H_+j  ], sB1[j  ])));
                float v1 = fast_tanh(fmaf(xy.x, sW1[j+1], fmaf(xy.y, sW1[H_+j+1], sB1[j+1])));
                *(u64t*)(A + p*WS + j) =
                    pk2(__uint_as_float(to_tf32(v0)), __uint_as_float(to_tf32(v1)));
            }
        }
        __syncthreads();

        mma_layer(A, W2s, sB2, l, mrow, ncol, 1);
        mma_layer(A, W3s, sB3, l, mrow, ncol, 0);

        // layer 4
        if (tid < 128){
            const float* Af = (const float*)(A + tid*WS);
            float acc = 0.f;
            #pragma unroll 8
            for (int k = 0; k < H_; k++) acc = fmaf(Af[k], sW4[k], acc);
            float ev = acc + sW4[H_];
            int p = p0 + tid;
            int e = p / NN_, n = p - e*NN_;
            float c00 = __ldg(&BDD[e*4 + 0]), c01 = __ldg(&BDD[e*4 + 1]);
            float c10 = __ldg(&BDD[e*4 + 2]), c11 = __ldg(&BDD[e*4 + 3]);
            g_evcat[e*K2_ + n]       = (c00 + c10) * ev;
            g_evcat[e*K2_ + NN_ + n] = (c01 + c11) * ev;
        }
        __syncthreads();
    }
}

// ============================================================
// Stage 2: tf32 mma.sync 128x128 tiles, 256 threads (8 warps, 32m x 64n each).
// u = -J*(evcat @ Acat^T); fused loss; last-block final reduce.
// ============================================================
__global__ __launch_bounds__(256, 2)
void gemm_loss(const float* __restrict__ J, const float* __restrict__ F,
               float* __restrict__ out){
    extern __shared__ __align__(16) uint32_t smg[];
    uint32_t* As = smg;              // [128][AK] tf32, m-major
    uint32_t* Bs = smg + 128*AK;     // [72][BN]  tf32, k-major (n fastest)
    const int tid = threadIdx.x;
    const int m0g = blockIdx.y * 128, n0g = blockIdx.x * 128;

    for (int idx = tid; idx < 128*K2_; idx += 256){
        int m = idx / K2_, k = idx - m*K2_;
        As[m*AK + k] = to_tf32(g_evcat[(m0g + m)*K2_ + k]);
    }
    for (int idx = tid; idx < 128*K2_; idx += 256){
        int n = idx / K2_, k = idx - n*K2_;
        Bs[k*BN + n] = to_tf32(g_Acat[(n0g + n)*K2_ + k]);
    }
    __syncthreads();

    const int w  = tid >> 5, l = tid & 31;
    const int lg = l >> 2, lt = l & 3;
    const int mrow = (w & 3) * 32, ncol = (w >> 2) * 64;

    float c[2][8][4];
    #pragma unroll
    for (int mt = 0; mt < 2; mt++)
        #pragma unroll
        for (int nt = 0; nt < 8; nt++)
            #pragma unroll
            for (int i = 0; i < 4; i++) c[mt][nt][i] = 0.f;

    #pragma unroll
    for (int kk = 0; kk < 9; kk++){
        const int k0 = kk * 8;
        uint32_t a[2][4];
        #pragma unroll
        for (int mt = 0; mt < 2; mt++){
            const int r = mrow + mt*16 + lg;
            a[mt][0] = As[ r     *AK + k0     + lt];
            a[mt][2] = As[ r     *AK + k0 + 4 + lt];
            a[mt][1] = As[(r + 8)*AK + k0     + lt];
            a[mt][3] = As[(r + 8)*AK + k0 + 4 + lt];
        }
        #pragma unroll
        for (int nt = 0; nt < 8; nt++){
            uint32_t b[2];
            const int n = ncol + nt*8 + lg;
            b[0] = Bs[(k0     + lt)*BN + n];
            b[1] = Bs[(k0 + 4 + lt)*BN + n];
            wmma8(c[0][nt], a[0], b);
            wmma8(c[1][nt], a[1], b);
        }
    }

    // fused epilogue on fragments: res = -J*dot - F; sum res^2
    float lsum = 0.f;
    #pragma unroll
    for (int mt = 0; mt < 2; mt++){
        const int r0 = mrow + mt*16 + lg;
        const int e0 = m0g + r0, e1 = e0 + 8;
        #pragma unroll
        for (int nt = 0; nt < 8; nt++){
            const int nn = n0g + ncol + nt*8 + 2*lt;
            const int s0 = nn / R_, s1 = (nn + 1) / R_;
            float2 f0 = __ldg((const float2*)(F + e0*SR_ + nn));
            float2 f1 = __ldg((const float2*)(F + e1*SR_ + nn));
            float ja0 = __ldg(&J[e0*S_ + s0]), jb0 = __ldg(&J[e0*S_ + s1]);
            float ja1 = __ldg(&J[e1*S_ + s0]), jb1 = __ldg(&J[e1*S_ + s1]);
            float r00 = -ja0*c[mt][nt][0] - f0.x;
            float r01 = -jb0*c[mt][nt][1] - f0.y;
            float r10 = -ja1*c[mt][nt][2] - f1.x;
            float r11 = -jb1*c[mt][nt][3] - f1.y;
            lsum += r00*r00 + r01*r01 + r10*r10 + r11*r11;
        }
    }

    __shared__ float red[256];
    red[tid] = lsum; __syncthreads();
    #pragma unroll
    for (int s = 128; s > 0; s >>= 1){
        if (tid < s) red[tid] += red[tid + s];
        __syncthreads();
    }

    __shared__ unsigned s_last;
    if (tid == 0){
        g_partial[blockIdx.y * GX + blockIdx.x] = red[0];
        __threadfence();
        unsigned t = atomicAdd(&g_count, 1u);
        s_last = (t == NPART - 1u) ? 1u : 0u;
    }
    __syncthreads();

    if (s_last){
        __shared__ double dred[256];
        double s = 0.0;
        for (int i = tid; i < NPART; i += 256) s += (double)g_partial[i];
        dred[tid] = s; __syncthreads();
        #pragma unroll
        for (int k = 128; k > 0; k >>= 1){
            if (tid < k) dred[tid] += dred[tid + k];
            __syncthreads();
        }
        if (tid == 0){
            out[0] = (float)(dred[0] / (double)R_);
            g_count = 0;
        }
    }
}

// ============================================================
extern "C" void kernel_launch(void* const* d_in, const int* in_sizes, int n_in,
                              void* d_out, int out_size){
    const float* nodes = (const float*)d_in[0];
    const float* W1    = (const float*)d_in[1];
    const float* b1    = (const float*)d_in[2];
    const float* W2    = (const float*)d_in[3];
    const float* b2    = (const float*)d_in[4];
    const float* W3    = (const float*)d_in[5];
    const float* b3    = (const float*)d_in[6];
    const float* W4    = (const float*)d_in[7];
    const float* b4    = (const float*)d_in[8];
    const float* Ixx   = (const float*)d_in[9];
    const float* Iyy   = (const float*)d_in[10];
    const float* BDD   = (const float*)d_in[11];
    const float* wq    = (const float*)d_in[12];
    const float* Base  = (const float*)d_in[13];
    const float* J     = (const float*)d_in[14];
    const float* F     = (const float*)d_in[15];

    const int s1_smem   = 3 * H_ * WS * 4;               // 202752 B
    const int gemm_smem = (128*AK + K2_*BN) * 4;         // 38912 + 38016 = 76928 B
    cudaFuncSetAttribute(stage1,    cudaFuncAttributeMaxDynamicSharedMemorySize, s1_smem);
    cudaFuncSetAttribute(gemm_loss, cudaFuncAttributeMaxDynamicSharedMemorySize, gemm_smem);

    stage1<<<STAGE1_BLOCKS, 256, s1_smem>>>(nodes, W1, b1, W2, b2, W3, b3, W4, b4,
                                            BDD, Ixx, Iyy, wq, Base);
    gemm_loss<<<dim3(GX, GY), 256, gemm_smem>>>(J, F, (float*)d_out);
}

// round 11
// speedup vs baseline: 5.9620x; 1.1571x over previous
#include <cuda_runtime.h>
#include <stdint.h>
#include <math.h>

#define E_    2048
#define S_    256
#define Q_    25
#define NN_   36
#define R_    15
#define H_    128
#define K2_   72
#define SR_   3840
#define NPTS  (E_*NN_)          // 73728
#define TPB   4
#define MLP_BLOCKS (NPTS/(128*TPB))      // 144
#define STAGE1_BLOCKS (MLP_BLOCKS + S_)  // 400
#define GX 30
#define GY 16
#define NPART (GX*GY)           // 480
#define WS 132                  // MLP smem word stride
#define AK 76                   // gemm_loss A k-stride (72+4)
#define BN 132                  // gemm_loss B n-stride
#define NJ 10                   // J slice width per n-tile

// ---- scratch ----
__device__ uint32_t g_evcat[E_*K2_];    // tf32 bits, [e][k]
__device__ uint32_t g_AcatT[K2_*SR_];   // tf32 bits, [k][sr]
__device__ float    g_partial[NPART];
__device__ unsigned g_count = 0;

typedef unsigned long long u64t;
__device__ __forceinline__ u64t pk2(float lo, float hi){
    u64t r; asm("mov.b64 %0,{%1,%2};" : "=l"(r) : "f"(lo), "f"(hi)); return r;
}
__device__ __forceinline__ float fast_tanh(float x){
    float y; asm("tanh.approx.f32 %0, %1;" : "=f"(y) : "f"(x)); return y;
}
__device__ __forceinline__ uint32_t to_tf32(float x){
    uint32_t v; asm("cvt.rna.tf32.f32 %0, %1;" : "=r"(v) : "f"(x)); return v;
}

__device__ __forceinline__ void wmma8(float* c, const uint32_t* a, const uint32_t* b){
    asm volatile("mma.sync.aligned.m16n8k8.row.col.f32.tf32.tf32.f32 "
        "{%0,%1,%2,%3},{%4,%5,%6,%7},{%8,%9},{%0,%1,%2,%3};"
        : "+f"(c[0]), "+f"(c[1]), "+f"(c[2]), "+f"(c[3])
        : "r"(a[0]), "r"(a[1]), "r"(a[2]), "r"(a[3]), "r"(b[0]), "r"(b[1]));
}

// ============================================================
// One MLP layer via mma.sync (layout proven in R9/R10).
// ============================================================
__device__ __forceinline__ void mma_layer(uint32_t* __restrict__ A,
                                          const uint32_t* __restrict__ W,
                                          const float* __restrict__ bias,
                                          int l, int mrow, int ncol, int out_tf32){
    float c[2][8][4];
    #pragma unroll
    for (int mt = 0; mt < 2; mt++)
        #pragma unroll
        for (int nt = 0; nt < 8; nt++)
            #pragma unroll
            for (int i = 0; i < 4; i++) c[mt][nt][i] = 0.f;

    const int lg = l >> 2, lt = l & 3;

    #pragma unroll 2
    for (int kk = 0; kk < 16; kk++){
        const int k0 = kk * 8;
        uint32_t a[2][4];
        #pragma unroll
        for (int mt = 0; mt < 2; mt++){
            const int r = mrow + mt*16 + lg;
            a[mt][0] = A[ r     *WS + k0     + lt];
            a[mt][2] = A[ r     *WS + k0 + 4 + lt];
            a[mt][1] = A[(r + 8)*WS + k0     + lt];
            a[mt][3] = A[(r + 8)*WS + k0 + 4 + lt];
        }
        #pragma unroll
        for (int nt = 0; nt < 8; nt++){
            uint32_t b[2];
            const int n = ncol + nt*8 + lg;
            b[0] = W[(k0     + lt)*WS + n];
            b[1] = W[(k0 + 4 + lt)*WS + n];
            wmma8(c[0][nt], a[0], b);
            wmma8(c[1][nt], a[1], b);
        }
    }
    __syncthreads();

    #pragma unroll
    for (int mt = 0; mt < 2; mt++){
        const int r = mrow + mt*16 + lg;
        #pragma unroll
        for (int nt = 0; nt < 8; nt++){
            const int n = ncol + nt*8 + 2*lt;
            const float b0 = bias[n], b1 = bias[n+1];
            float v0 = fast_tanh(c[mt][nt][0] + b0);
            float v1 = fast_tanh(c[mt][nt][1] + b1);
            float v2 = fast_tanh(c[mt][nt][2] + b0);
            float v3 = fast_tanh(c[mt][nt][3] + b1);
            uint32_t u0, u1, u2, u3;
            if (out_tf32){
                u0 = to_tf32(v0); u1 = to_tf32(v1); u2 = to_tf32(v2); u3 = to_tf32(v3);
            } else {
                u0 = __float_as_uint(v0); u1 = __float_as_uint(v1);
                u2 = __float_as_uint(v2); u3 = __float_as_uint(v3);
            }
            *(u64t*)(A +  r     *WS + n) = pk2(__uint_as_float(u0), __uint_as_float(u1));
            *(u64t*)(A + (r + 8)*WS + n) = pk2(__uint_as_float(u2), __uint_as_float(u3));
        }
    }
    __syncthreads();
}

// ============================================================
// Stage 1: blocks [0,144) MLP (4x128 pts, weights staged once);
//          blocks [144,400) build AcatT (tf32, transposed).
// ============================================================
__global__ __launch_bounds__(256, 1)
void stage1(const float* __restrict__ nodes,
            const float* __restrict__ W1, const float* __restrict__ b1,
            const float* __restrict__ W2, const float* __restrict__ b2,
            const float* __restrict__ W3, const float* __restrict__ b3,
            const float* __restrict__ W4, const float* __restrict__ b4,
            const float* __restrict__ BDD,
            const float* __restrict__ Ixx, const float* __restrict__ Iyy,
            const float* __restrict__ wq,  const float* __restrict__ Base){
    extern __shared__ __align__(16) uint32_t smw[];
    const int tid = threadIdx.x;

    if (blockIdx.x >= MLP_BLOCKS){
        const int s = blockIdx.x - MLP_BLOCKS;
        float* WB  = (float*)smw;
        float* sI0 = WB  + Q_*R_;
        float* sI1 = sI0 + Q_*NN_;
        for (int i = tid; i < Q_*R_; i += 256){
            int q = i / R_, r = i - q*R_;
            WB[i] = wq[q] * Base[q*R_ + r];
        }
        for (int i = tid; i < Q_*NN_; i += 256){
            sI0[i] = Ixx[s*Q_*NN_ + i];
            sI1[i] = Iyy[s*Q_*NN_ + i];
        }
        __syncthreads();
        for (int idx = tid; idx < R_*K2_; idx += 256){
            int r = idx / K2_, n = idx - r*K2_;
            const float* I = (n < NN_) ? sI0 : sI1;
            int nn = (n < NN_) ? n : (n - NN_);
            float acc = 0.f;
            #pragma unroll
            for (int q = 0; q < Q_; q++) acc += WB[q*R_ + r] * I[q*NN_ + nn];
            g_AcatT[n*SR_ + s*R_ + r] = to_tf32(acc);
        }
        return;
    }

    // ---------- MLP ----------
    uint32_t* W2s = smw;
    uint32_t* W3s = smw + H_*WS;
    uint32_t* A   = smw + 2*H_*WS;
    __shared__ float sW1[2*H_], sB1[H_], sB2[H_], sB3[H_], sW4[H_+1];

    const int w  = tid >> 5, l = tid & 31;
    const int mrow = (w & 3) * 32, ncol = (w >> 2) * 64;

    for (int i = tid; i < H_*H_; i += 256){
        int k = i >> 7, n = i & 127;
        W2s[k*WS + n] = to_tf32(W2[i]);
        W3s[k*WS + n] = to_tf32(W3[i]);
    }
    if (tid < 2*H_) sW1[tid] = W1[tid];
    if (tid < H_){ sB1[tid] = b1[tid]; sB2[tid] = b2[tid]; sB3[tid] = b3[tid]; sW4[tid] = W4[tid]; }
    if (tid == 0) sW4[H_] = b4[0];
    __syncthreads();

    for (int t = 0; t < TPB; t++){
        const int p0 = (blockIdx.x * TPB + t) * 128;

        {
            const int p  = tid >> 1;
            const int jh = (tid & 1) * 64;
            float2 xy = ((const float2*)nodes)[p0 + p];
            #pragma unroll 8
            for (int j = jh; j < jh + 64; j += 2){
                float v0 = fast_tanh(fmaf(xy.x, sW1[j  ], fmaf(xy.y, sW1[H_+j  ], sB1[j  ])));
                float v1 = fast_tanh(fmaf(xy.x, sW1[j+1], fmaf(xy.y, sW1[H_+j+1], sB1[j+1])));
                *(u64t*)(A + p*WS + j) =
                    pk2(__uint_as_float(to_tf32(v0)), __uint_as_float(to_tf32(v1)));
            }
        }
        __syncthreads();

        mma_layer(A, W2s, sB2, l, mrow, ncol, 1);
        mma_layer(A, W3s, sB3, l, mrow, ncol, 0);

        if (tid < 128){
            const float* Af = (const float*)(A + tid*WS);
            float acc = 0.f;
            #pragma unroll 8
            for (int k = 0; k < H_; k++) acc = fmaf(Af[k], sW4[k], acc);
            float ev = acc + sW4[H_];
            int p = p0 + tid;
            int e = p / NN_, n = p - e*NN_;
            float c00 = __ldg(&BDD[e*4 + 0]), c01 = __ldg(&BDD[e*4 + 1]);
            float c10 = __ldg(&BDD[e*4 + 2]), c11 = __ldg(&BDD[e*4 + 3]);
            g_evcat[e*K2_ + n]       = to_tf32((c00 + c10) * ev);
            g_evcat[e*K2_ + NN_ + n] = to_tf32((c01 + c11) * ev);
        }
        __syncthreads();
    }
}

// ============================================================
// Stage 2: tf32 mma.sync 128x128 tiles, 256 threads.
// Staging = pure uint4 copies (producers pre-converted/transposed).
// -J staged into smem; fused loss; last-block final reduce.
// ============================================================
__global__ __launch_bounds__(256, 2)
void gemm_loss(const float* __restrict__ J, const float* __restrict__ F,
               float* __restrict__ out){
    extern __shared__ __align__(16) uint32_t smg[];
    uint32_t* As = smg;                    // [128][AK]
    uint32_t* Bs = smg + 128*AK;           // [72][BN]
    float*    Js = (float*)(smg + 128*AK + K2_*BN);   // [128][NJ] = -J slice
    const int tid = threadIdx.x;
    const int m0g = blockIdx.y * 128, n0g = blockIdx.x * 128;
    const int s0  = n0g / R_;

    // vector staging: evcat rows (18 uint4 each), AcatT rows (32 uint4 each)
    for (int idx = tid; idx < 128*18; idx += 256){
        int m = idx / 18, q = idx - m*18;
        ((uint4*)(As + m*AK))[q] = ((const uint4*)(g_evcat + (m0g + m)*K2_))[q];
    }
    for (int idx = tid; idx < K2_*32; idx += 256){
        int k = idx / 32, q = idx - k*32;
        ((uint4*)(Bs + k*BN))[q] = ((const uint4*)(g_AcatT + k*SR_ + n0g))[q];
    }
    for (int idx = tid; idx < 128*NJ; idx += 256){
        int m = idx / NJ, ss = idx - m*NJ;
        int s = s0 + ss;
        Js[idx] = (s < S_) ? -J[(m0g + m)*S_ + s] : 0.f;
    }
    __syncthreads();

    const int w  = tid >> 5, l = tid & 31;
    const int lg = l >> 2, lt = l & 3;
    const int mrow = (w & 3) * 32, ncol = (w >> 2) * 64;

    float c[2][8][4];
    #pragma unroll
    for (int mt = 0; mt < 2; mt++)
        #pragma unroll
        for (int nt = 0; nt < 8; nt++)
            #pragma unroll
            for (int i = 0; i < 4; i++) c[mt][nt][i] = 0.f;

    #pragma unroll
    for (int kk = 0; kk < 9; kk++){
        const int k0 = kk * 8;
        uint32_t a[2][4];
        #pragma unroll
        for (int mt = 0; mt < 2; mt++){
            const int r = mrow + mt*16 + lg;
            a[mt][0] = As[ r     *AK + k0     + lt];
            a[mt][2] = As[ r     *AK + k0 + 4 + lt];
            a[mt][1] = As[(r + 8)*AK + k0     + lt];
            a[mt][3] = As[(r + 8)*AK + k0 + 4 + lt];
        }
        #pragma unroll
        for (int nt = 0; nt < 8; nt++){
            uint32_t b[2];
            const int n = ncol + nt*8 + lg;
            b[0] = Bs[(k0     + lt)*BN + n];
            b[1] = Bs[(k0 + 4 + lt)*BN + n];
            wmma8(c[0][nt], a[0], b);
            wmma8(c[1][nt], a[1], b);
        }
    }

    // fused epilogue: res = (-J)*dot - F; sum res^2
    float lsum = 0.f;
    #pragma unroll
    for (int mt = 0; mt < 2; mt++){
        const int r0 = mrow + mt*16 + lg;
        const int e0 = m0g + r0, e1 = e0 + 8;
        #pragma unroll
        for (int nt = 0; nt < 8; nt++){
            const int nl = ncol + nt*8 + 2*lt;
            const int sA = (n0g + nl) / R_ - s0;
            const int sB = (n0g + nl + 1) / R_ - s0;
            float2 f0 = __ldg((const float2*)(F + e0*SR_ + n0g + nl));
            float2 f1 = __ldg((const float2*)(F + e1*SR_ + n0g + nl));
            float ja0 = Js[ r0      *NJ + sA], jb0 = Js[ r0      *NJ + sB];
            float ja1 = Js[(r0 + 8) *NJ + sA], jb1 = Js[(r0 + 8) *NJ + sB];
            float r00 = fmaf(ja0, c[mt][nt][0], -f0.x);
            float r01 = fmaf(jb0, c[mt][nt][1], -f0.y);
            float r10 = fmaf(ja1, c[mt][nt][2], -f1.x);
            float r11 = fmaf(jb1, c[mt][nt][3], -f1.y);
            lsum = fmaf(r00, r00, lsum);
            lsum = fmaf(r01, r01, lsum);
            lsum = fmaf(r10, r10, lsum);
            lsum = fmaf(r11, r11, lsum);
        }
    }

    __shared__ float red[256];
    red[tid] = lsum; __syncthreads();
    #pragma unroll
    for (int s = 128; s > 0; s >>= 1){
        if (tid < s) red[tid] += red[tid + s];
        __syncthreads();
    }

    __shared__ unsigned s_last;
    if (tid == 0){
        g_partial[blockIdx.y * GX + blockIdx.x] = red[0];
        __threadfence();
        unsigned t = atomicAdd(&g_count, 1u);
        s_last = (t == NPART - 1u) ? 1u : 0u;
    }
    __syncthreads();

    if (s_last){
        __shared__ double dred[256];
        double s = 0.0;
        for (int i = tid; i < NPART; i += 256) s += (double)g_partial[i];
        dred[tid] = s; __syncthreads();
        #pragma unroll
        for (int k = 128; k > 0; k >>= 1){
            if (tid < k) dred[tid] += dred[tid + k];
            __syncthreads();
        }
        if (tid == 0){
            out[0] = (float)(dred[0] / (double)R_);
            g_count = 0;
        }
    }
}

// ============================================================
extern "C" void kernel_launch(void* const* d_in, const int* in_sizes, int n_in,
                              void* d_out, int out_size){
    const float* nodes = (const float*)d_in[0];
    const float* W1    = (const float*)d_in[1];
    const float* b1    = (const float*)d_in[2];
    const float* W2    = (const float*)d_in[3];
    const float* b2    = (const float*)d_in[4];
    const float* W3    = (const float*)d_in[5];
    const float* b3    = (const float*)d_in[6];
    const float* W4    = (const float*)d_in[7];
    const float* b4    = (const float*)d_in[8];
    const float* Ixx   = (const float*)d_in[9];
    const float* Iyy   = (const float*)d_in[10];
    const float* BDD   = (const float*)d_in[11];
    const float* wq    = (const float*)d_in[12];
    const float* Base  = (const float*)d_in[13];
    const float* J     = (const float*)d_in[14];
    const float* F     = (const float*)d_in[15];

    const int s1_smem   = 3 * H_ * WS * 4;                        // 202752 B
    const int gemm_smem = (128*AK + K2_*BN + 128*NJ) * 4;         // 82048 B
    cudaFuncSetAttribute(stage1,    cudaFuncAttributeMaxDynamicSharedMemorySize, s1_smem);
    cudaFuncSetAttribute(gemm_loss, cudaFuncAttributeMaxDynamicSharedMemorySize, gemm_smem);

    stage1<<<STAGE1_BLOCKS, 256, s1_smem>>>(nodes, W1, b1, W2, b2, W3, b3, W4, b4,
                                            BDD, Ixx, Iyy, wq, Base);
    gemm_loss<<<dim3(GX, GY), 256, gemm_smem>>>(J, F, (float*)d_out);
}

// round 12
// speedup vs baseline: 6.7866x; 1.1383x over previous
#include <cuda_runtime.h>
#include <cuda_fp16.h>
#include <stdint.h>
#include <math.h>

#define E_    2048
#define S_    256
#define Q_    25
#define NN_   36
#define R_    15
#define H_    128
#define K2_   72
#define KP_   80            // K2 padded to multiple of 16
#define SR_   3840
#define NPTS  (E_*NN_)      // 73728
#define TPB   4
#define MLP_BLOCKS (NPTS/(128*TPB))      // 144
#define STAGE1_BLOCKS (MLP_BLOCKS + S_)  // 400
#define GX 60               // N tiles (3840/64)
#define GY 16               // M tiles (2048/128)
#define NPART (GX*GY)       // 960
#define WSU 68              // MLP smem stride in u32 (128 halves + 8 pad)
#define GKU 44              // gemm tile stride in u32 (80 halves + 8 pad)
#define NJ 6                // J slice width per 64-wide n-tile

// ---- scratch ----
__device__ __half   g_evH[E_*KP_];      // [e][k] fp16, k>=72 zeroed
__device__ __half   g_AcatH[SR_*KP_];   // [sr][k] fp16, k>=72 zeroed
__device__ float    g_partial[NPART];
__device__ unsigned g_count = 0;

__device__ __forceinline__ float fast_tanh(float x){
    float y; asm("tanh.approx.f32 %0, %1;" : "=f"(y) : "f"(x)); return y;
}
__device__ __forceinline__ uint32_t pkh(float lo, float hi){
    __half2 h = __floats2half2_rn(lo, hi);
    return *(uint32_t*)&h;
}

// fp16 MMA: D(16x8,f32) += A(16x16,row) * B(16x8,col)
__device__ __forceinline__ void hmma16(float* c, const uint32_t* a, const uint32_t* b){
    asm volatile("mma.sync.aligned.m16n8k16.row.col.f32.f16.f16.f32 "
        "{%0,%1,%2,%3},{%4,%5,%6,%7},{%8,%9},{%0,%1,%2,%3};"
        : "+f"(c[0]), "+f"(c[1]), "+f"(c[2]), "+f"(c[3])
        : "r"(a[0]), "r"(a[1]), "r"(a[2]), "r"(a[3]), "r"(b[0]), "r"(b[1]));
}

// ============================================================
// One MLP layer: A[128 pts x 128 k](fp16) @ Wt (as [n][k] fp16)
// -> tanh(.+bias) -> overwrite A. 8 warps: rows (w&3)*32, cols (w>>2)*64.
// ============================================================
__device__ __forceinline__ void mma_layer(uint32_t* __restrict__ A,
                                          const uint32_t* __restrict__ Wt,
                                          const float* __restrict__ bias,
                                          int l, int mrow, int ncol){
    float c[2][8][4];
    #pragma unroll
    for (int mt = 0; mt < 2; mt++)
        #pragma unroll
        for (int nt = 0; nt < 8; nt++)
            #pragma unroll
            for (int i = 0; i < 4; i++) c[mt][nt][i] = 0.f;

    const int g = l >> 2, t = l & 3;

    #pragma unroll
    for (int kk = 0; kk < 8; kk++){
        const int kw = kk * 8;   // u32 offset = k0/2
        uint32_t a[2][4];
        #pragma unroll
        for (int mt = 0; mt < 2; mt++){
            const int r = mrow + mt*16 + g;
            a[mt][0] = A[ r     *WSU + kw     + t];
            a[mt][1] = A[(r + 8)*WSU + kw     + t];
            a[mt][2] = A[ r     *WSU + kw + 4 + t];
            a[mt][3] = A[(r + 8)*WSU + kw + 4 + t];
        }
        #pragma unroll
        for (int nt = 0; nt < 8; nt++){
            const int n = ncol + nt*8 + g;
            uint32_t b[2];
            b[0] = Wt[n*WSU + kw     + t];
            b[1] = Wt[n*WSU + kw + 4 + t];
            hmma16(c[0][nt], a[0], b);
            hmma16(c[1][nt], a[1], b);
        }
    }
    __syncthreads();

    #pragma unroll
    for (int mt = 0; mt < 2; mt++){
        const int r = mrow + mt*16 + g;
        #pragma unroll
        for (int nt = 0; nt < 8; nt++){
            const int n = ncol + nt*8 + 2*t;
            const float b0 = bias[n], b1 = bias[n+1];
            const int cw = (ncol + nt*8)/2 + t;
            A[ r     *WSU + cw] = pkh(fast_tanh(c[mt][nt][0] + b0),
                                      fast_tanh(c[mt][nt][1] + b1));
            A[(r + 8)*WSU + cw] = pkh(fast_tanh(c[mt][nt][2] + b0),
                                      fast_tanh(c[mt][nt][3] + b1));
        }
    }
    __syncthreads();
}

// ============================================================
// Stage 1: blocks [0,144) MLP (4x128 pts); blocks [144,400) AcatH.
// ============================================================
__global__ __launch_bounds__(256, 2)
void stage1(const float* __restrict__ nodes,
            const float* __restrict__ W1, const float* __restrict__ b1,
            const float* __restrict__ W2, const float* __restrict__ b2,
            const float* __restrict__ W3, const float* __restrict__ b3,
            const float* __restrict__ W4, const float* __restrict__ b4,
            const float* __restrict__ BDD,
            const float* __restrict__ Ixx, const float* __restrict__ Iyy,
            const float* __restrict__ wq,  const float* __restrict__ Base){
    extern __shared__ __align__(16) uint32_t smw[];
    const int tid = threadIdx.x;

    if (blockIdx.x >= MLP_BLOCKS){
        const int s = blockIdx.x - MLP_BLOCKS;
        float* WB  = (float*)smw;
        float* sI0 = WB  + Q_*R_;
        float* sI1 = sI0 + Q_*NN_;
        for (int i = tid; i < Q_*R_; i += 256){
            int q = i / R_, r = i - q*R_;
            WB[i] = wq[q] * Base[q*R_ + r];
        }
        for (int i = tid; i < Q_*NN_; i += 256){
            sI0[i] = Ixx[s*Q_*NN_ + i];
            sI1[i] = Iyy[s*Q_*NN_ + i];
        }
        __syncthreads();
        for (int idx = tid; idx < R_*K2_; idx += 256){
            int r = idx / K2_, n = idx - r*K2_;
            const float* I = (n < NN_) ? sI0 : sI1;
            int nn = (n < NN_) ? n : (n - NN_);
            float acc = 0.f;
            #pragma unroll
            for (int q = 0; q < Q_; q++) acc += WB[q*R_ + r] * I[q*NN_ + nn];
            const int sr = s*R_ + r;
            g_AcatH[sr*KP_ + n] = __float2half(acc);
            if (n < KP_ - K2_) g_AcatH[sr*KP_ + K2_ + n] = __float2half(0.f);
        }
        return;
    }

    // ---------- MLP ----------
    uint32_t* W2t = smw;                  // [128 n][WSU] fp16 pairs (k-contig)
    uint32_t* W3t = smw + H_*WSU;
    uint32_t* A   = smw + 2*H_*WSU;       // [128 pts][WSU]
    __shared__ float sW1[2*H_], sB1[H_], sB2[H_], sB3[H_], sW4[H_+1];

    const int w = tid >> 5, l = tid & 31;
    const int mrow = (w & 3) * 32, ncol = (w >> 2) * 64;

    // stage transposed fp16 weights: Wt[n][k]
    for (int i = tid; i < H_*H_; i += 256){
        int k = i >> 7, n = i & 127;
        ((__half*)W2t)[n*(2*WSU) + k] = __float2half(W2[i]);
        ((__half*)W3t)[n*(2*WSU) + k] = __float2half(W3[i]);
    }
    if (tid < 2*H_) sW1[tid] = W1[tid];
    if (tid < H_){ sB1[tid] = b1[tid]; sB2[tid] = b2[tid]; sB3[tid] = b3[tid]; sW4[tid] = W4[tid]; }
    if (tid == 0) sW4[H_] = b4[0];
    __syncthreads();

    for (int t = 0; t < TPB; t++){
        const int p0 = (blockIdx.x * TPB + t) * 128;

        // layer 1
        {
            const int p  = tid >> 1;
            const int jh = (tid & 1) * 64;
            float2 xy = ((const float2*)nodes)[p0 + p];
            #pragma unroll 8
            for (int j = jh; j < jh + 64; j += 2){
                float v0 = fast_tanh(fmaf(xy.x, sW1[j  ], fmaf(xy.y, sW1[H_+j  ], sB1[j  ])));
                float v1 = fast_tanh(fmaf(xy.x, sW1[j+1], fmaf(xy.y, sW1[H_+j+1], sB1[j+1])));
                A[p*WSU + (j >> 1)] = pkh(v0, v1);
            }
        }
        __syncthreads();

        mma_layer(A, W2t, sB2, l, mrow, ncol);
        mma_layer(A, W3t, sB3, l, mrow, ncol);

        // layer 4 + evcat (fp16 out, zero-padded k 72..79)
        if (tid < 128){
            const uint32_t* Af = A + tid*WSU;
            float acc = 0.f;
            #pragma unroll 8
            for (int k = 0; k < H_/2; k++){
                __half2 h = *(const __half2*)&Af[k];
                float2 f = __half22float2(h);
                acc = fmaf(f.x, sW4[2*k], acc);
                acc = fmaf(f.y, sW4[2*k+1], acc);
            }
            float ev = acc + sW4[H_];
            int p = p0 + tid;
            int e = p / NN_, n = p - e*NN_;
            float c00 = __ldg(&BDD[e*4 + 0]), c01 = __ldg(&BDD[e*4 + 1]);
            float c10 = __ldg(&BDD[e*4 + 2]), c11 = __ldg(&BDD[e*4 + 3]);
            g_evH[e*KP_ + n]       = __float2half((c00 + c10) * ev);
            g_evH[e*KP_ + NN_ + n] = __float2half((c01 + c11) * ev);
            if (n < KP_ - K2_) g_evH[e*KP_ + K2_ + n] = __float2half(0.f);
        }
        __syncthreads();
    }
}

// ============================================================
// Stage 2: fp16 mma 128m x 64n tiles, 256 threads (8 warps, 32x32 each).
// ============================================================
__global__ __launch_bounds__(256, 3)
void gemm_loss(const float* __restrict__ J, const float* __restrict__ F,
               float* __restrict__ out){
    extern __shared__ __align__(16) uint32_t smg[];
    uint32_t* As = smg;                    // [128 m][GKU]
    uint32_t* Bs = smg + 128*GKU;          // [64 n][GKU]
    float*    Js = (float*)(smg + 128*GKU + 64*GKU);   // [128][NJ] = -J
    const int tid = threadIdx.x;
    const int m0g = blockIdx.y * 128, n0g = blockIdx.x * 64;
    const int s0  = n0g / R_;

    for (int idx = tid; idx < 128*10; idx += 256){
        int m = idx / 10, q = idx - m*10;
        ((uint4*)(As + m*GKU))[q] = ((const uint4*)(g_evH + (m0g + m)*KP_))[q];
    }
    for (int idx = tid; idx < 64*10; idx += 256){
        int n = idx / 10, q = idx - n*10;
        ((uint4*)(Bs + n*GKU))[q] = ((const uint4*)(g_AcatH + (n0g + n)*KP_))[q];
    }
    for (int idx = tid; idx < 128*NJ; idx += 256){
        int m = idx / NJ, ss = idx - m*NJ;
        int s = s0 + ss;
        Js[idx] = (s < S_) ? -J[(m0g + m)*S_ + s] : 0.f;
    }
    __syncthreads();

    const int w = tid >> 5, l = tid & 31;
    const int g = l >> 2, t = l & 3;
    const int mrow = (w & 3) * 32, ncol = (w >> 2) * 32;

    float c[2][4][4];
    #pragma unroll
    for (int mt = 0; mt < 2; mt++)
        #pragma unroll
        for (int nt = 0; nt < 4; nt++)
            #pragma unroll
            for (int i = 0; i < 4; i++) c[mt][nt][i] = 0.f;

    #pragma unroll
    for (int kk = 0; kk < 5; kk++){
        const int kw = kk * 8;
        uint32_t a[2][4];
        #pragma unroll
        for (int mt = 0; mt < 2; mt++){
            const int r = mrow + mt*16 + g;
            a[mt][0] = As[ r     *GKU + kw     + t];
            a[mt][1] = As[(r + 8)*GKU + kw     + t];
            a[mt][2] = As[ r     *GKU + kw + 4 + t];
            a[mt][3] = As[(r + 8)*GKU + kw + 4 + t];
        }
        #pragma unroll
        for (int nt = 0; nt < 4; nt++){
            const int n = ncol + nt*8 + g;
            uint32_t b[2];
            b[0] = Bs[n*GKU + kw     + t];
            b[1] = Bs[n*GKU + kw + 4 + t];
            hmma16(c[0][nt], a[0], b);
            hmma16(c[1][nt], a[1], b);
        }
    }

    // fused epilogue: res = (-J)*dot - F; sum res^2
    float lsum = 0.f;
    #pragma unroll
    for (int mt = 0; mt < 2; mt++){
        const int r0 = mrow + mt*16 + g;
        const int e0 = m0g + r0, e1 = e0 + 8;
        #pragma unroll
        for (int nt = 0; nt < 4; nt++){
            const int nl = ncol + nt*8 + 2*t;
            const int sA = (n0g + nl) / R_ - s0;
            const int sB = (n0g + nl + 1) / R_ - s0;
            float2 f0 = __ldg((const float2*)(F + e0*SR_ + n0g + nl));
            float2 f1 = __ldg((const float2*)(F + e1*SR_ + n0g + nl));
            float ja0 = Js[ r0      *NJ + sA], jb0 = Js[ r0      *NJ + sB];
            float ja1 = Js[(r0 + 8) *NJ + sA], jb1 = Js[(r0 + 8) *NJ + sB];
            float r00 = fmaf(ja0, c[mt][nt][0], -f0.x);
            float r01 = fmaf(jb0, c[mt][nt][1], -f0.y);
            float r10 = fmaf(ja1, c[mt][nt][2], -f1.x);
            float r11 = fmaf(jb1, c[mt][nt][3], -f1.y);
            lsum = fmaf(r00, r00, lsum);
            lsum = fmaf(r01, r01, lsum);
            lsum = fmaf(r10, r10, lsum);
            lsum = fmaf(r11, r11, lsum);
        }
    }

    __shared__ float red[256];
    red[tid] = lsum; __syncthreads();
    #pragma unroll
    for (int s = 128; s > 0; s >>= 1){
        if (tid < s) red[tid] += red[tid + s];
        __syncthreads();
    }

    __shared__ unsigned s_last;
    if (tid == 0){
        g_partial[blockIdx.y * GX + blockIdx.x] = red[0];
        __threadfence();
        unsigned t2 = atomicAdd(&g_count, 1u);
        s_last = (t2 == NPART - 1u) ? 1u : 0u;
    }
    __syncthreads();

    if (s_last){
        __shared__ double dred[256];
        double s = 0.0;
        for (int i = tid; i < NPART; i += 256) s += (double)g_partial[i];
        dred[tid] = s; __syncthreads();
        #pragma unroll
        for (int k = 128; k > 0; k >>= 1){
            if (tid < k) dred[tid] += dred[tid + k];
            __syncthreads();
        }
        if (tid == 0){
            out[0] = (float)(dred[0] / (double)R_);
            g_count = 0;
        }
    }
}

// ============================================================
extern "C" void kernel_launch(void* const* d_in, const int* in_sizes, int n_in,
                              void* d_out, int out_size){
    const float* nodes = (const float*)d_in[0];
    const float* W1    = (const float*)d_in[1];
    const float* b1    = (const float*)d_in[2];
    const float* W2    = (const float*)d_in[3];
    const float* b2    = (const float*)d_in[4];
    const float* W3    = (const float*)d_in[5];
    const float* b3    = (const float*)d_in[6];
    const float* W4    = (const float*)d_in[7];
    const float* b4    = (const float*)d_in[8];
    const float* Ixx   = (const float*)d_in[9];
    const float* Iyy   = (const float*)d_in[10];
    const float* BDD   = (const float*)d_in[11];
    const float* wq    = (const float*)d_in[12];
    const float* Base  = (const float*)d_in[13];
    const float* J     = (const float*)d_in[14];
    const float* F     = (const float*)d_in[15];

    const int s1_smem   = 3 * H_ * WSU * 4;                       // 104448 B
    const int gemm_smem = (128*GKU + 64*GKU + 128*NJ) * 4;        // 36864 B
    cudaFuncSetAttribute(stage1,    cudaFuncAttributeMaxDynamicSharedMemorySize, s1_smem);
    cudaFuncSetAttribute(gemm_loss, cudaFuncAttributeMaxDynamicSharedMemorySize, gemm_smem);

    stage1<<<STAGE1_BLOCKS, 256, s1_smem>>>(nodes, W1, b1, W2, b2, W3, b3, W4, b4,
                                            BDD, Ixx, Iyy, wq, Base);
    gemm_loss<<<dim3(GX, GY), 256, gemm_smem>>>(J, F, (float*)d_out);
}

// round 13
// speedup vs baseline: 9.7053x; 1.4301x over previous
#include <cuda_runtime.h>
#include <cuda_fp16.h>
#include <stdint.h>
#include <math.h>

#define E_    2048
#define S_    256
#define Q_    25
#define NN_   36
#define R_    15
#define H_    128
#define K2_   72
#define KP_   80
#define SR_   3840
#define NPTS  (E_*NN_)      // 73728
#define TPB   2
#define MLP_BLOCKS (NPTS/(128*TPB))      // 288
#define STAGE1_BLOCKS (MLP_BLOCKS + S_)  // 544
#define GX 60               // N tiles (3840/64)
#define GY 16               // M tiles (2048/128)
#define NPART (GX*GY)       // 960
#define WSU 68              // MLP smem stride (u32)
#define GKU 44              // gemm A/B stride (u32)
#define FS  68              // F smem stride (floats), 16B-aligned rows
#define NJ 6

// ---- scratch ----
__device__ __half   g_evH[E_*KP_];
__device__ __half   g_AcatH[SR_*KP_];
__device__ float    g_partial[NPART];
__device__ unsigned g_count = 0;

__device__ __forceinline__ float fast_tanh(float x){
    float y; asm("tanh.approx.f32 %0, %1;" : "=f"(y) : "f"(x)); return y;
}
__device__ __forceinline__ uint32_t pkh(float lo, float hi){
    __half2 h = __floats2half2_rn(lo, hi);
    return *(uint32_t*)&h;
}
__device__ __forceinline__ void cpa16(uint32_t saddr, const void* g){
    asm volatile("cp.async.ca.shared.global [%0], [%1], 16;" :: "r"(saddr), "l"(g));
}
#define CPA_COMMIT() asm volatile("cp.async.commit_group;" ::: "memory")
#define CPA_WAIT1()  asm volatile("cp.async.wait_group 1;" ::: "memory")
#define CPA_WAIT0()  asm volatile("cp.async.wait_group 0;" ::: "memory")

__device__ __forceinline__ void hmma16(float* c, const uint32_t* a, const uint32_t* b){
    asm volatile("mma.sync.aligned.m16n8k16.row.col.f32.f16.f16.f32 "
        "{%0,%1,%2,%3},{%4,%5,%6,%7},{%8,%9},{%0,%1,%2,%3};"
        : "+f"(c[0]), "+f"(c[1]), "+f"(c[2]), "+f"(c[3])
        : "r"(a[0]), "r"(a[1]), "r"(a[2]), "r"(a[3]), "r"(b[0]), "r"(b[1]));
}

// ============================================================
// One MLP layer (fp16 mma, proven R12 layout).
// ============================================================
__device__ __forceinline__ void mma_layer(uint32_t* __restrict__ A,
                                          const uint32_t* __restrict__ Wt,
                                          const float* __restrict__ bias,
                                          int l, int mrow, int ncol){
    float c[2][8][4];
    #pragma unroll
    for (int mt = 0; mt < 2; mt++)
        #pragma unroll
        for (int nt = 0; nt < 8; nt++)
            #pragma unroll
            for (int i = 0; i < 4; i++) c[mt][nt][i] = 0.f;

    const int g = l >> 2, t = l & 3;

    #pragma unroll
    for (int kk = 0; kk < 8; kk++){
        const int kw = kk * 8;
        uint32_t a[2][4];
        #pragma unroll
        for (int mt = 0; mt < 2; mt++){
            const int r = mrow + mt*16 + g;
            a[mt][0] = A[ r     *WSU + kw     + t];
            a[mt][1] = A[(r + 8)*WSU + kw     + t];
            a[mt][2] = A[ r     *WSU + kw + 4 + t];
            a[mt][3] = A[(r + 8)*WSU + kw + 4 + t];
        }
        #pragma unroll
        for (int nt = 0; nt < 8; nt++){
            const int n = ncol + nt*8 + g;
            uint32_t b[2];
            b[0] = Wt[n*WSU + kw     + t];
            b[1] = Wt[n*WSU + kw + 4 + t];
            hmma16(c[0][nt], a[0], b);
            hmma16(c[1][nt], a[1], b);
        }
    }
    __syncthreads();

    #pragma unroll
    for (int mt = 0; mt < 2; mt++){
        const int r = mrow + mt*16 + g;
        #pragma unroll
        for (int nt = 0; nt < 8; nt++){
            const int n = ncol + nt*8 + 2*t;
            const float b0 = bias[n], b1 = bias[n+1];
            const int cw = (ncol + nt*8)/2 + t;
            A[ r     *WSU + cw] = pkh(fast_tanh(c[mt][nt][0] + b0),
                                      fast_tanh(c[mt][nt][1] + b1));
            A[(r + 8)*WSU + cw] = pkh(fast_tanh(c[mt][nt][2] + b0),
                                      fast_tanh(c[mt][nt][3] + b1));
        }
    }
    __syncthreads();
}

// ============================================================
// Stage 1: blocks [0,288) MLP (2x128 pts); blocks [288,544) AcatH.
// ============================================================
__global__ __launch_bounds__(256, 2)
void stage1(const float* __restrict__ nodes,
            const float* __restrict__ W1, const float* __restrict__ b1,
            const float* __restrict__ W2, const float* __restrict__ b2,
            const float* __restrict__ W3, const float* __restrict__ b3,
            const float* __restrict__ W4, const float* __restrict__ b4,
            const float* __restrict__ BDD,
            const float* __restrict__ Ixx, const float* __restrict__ Iyy,
            const float* __restrict__ wq,  const float* __restrict__ Base){
    extern __shared__ __align__(16) uint32_t smw[];
    const int tid = threadIdx.x;

    if (blockIdx.x >= MLP_BLOCKS){
        const int s = blockIdx.x - MLP_BLOCKS;
        float* WB  = (float*)smw;
        float* sI0 = WB  + Q_*R_;
        float* sI1 = sI0 + Q_*NN_;
        for (int i = tid; i < Q_*R_; i += 256){
            int q = i / R_, r = i - q*R_;
            WB[i] = wq[q] * Base[q*R_ + r];
        }
        for (int i = tid; i < Q_*NN_; i += 256){
            sI0[i] = Ixx[s*Q_*NN_ + i];
            sI1[i] = Iyy[s*Q_*NN_ + i];
        }
        __syncthreads();
        for (int idx = tid; idx < R_*K2_; idx += 256){
            int r = idx / K2_, n = idx - r*K2_;
            const float* I = (n < NN_) ? sI0 : sI1;
            int nn = (n < NN_) ? n : (n - NN_);
            float acc = 0.f;
            #pragma unroll
            for (int q = 0; q < Q_; q++) acc += WB[q*R_ + r] * I[q*NN_ + nn];
            const int sr = s*R_ + r;
            g_AcatH[sr*KP_ + n] = __float2half(acc);
            if (n < KP_ - K2_) g_AcatH[sr*KP_ + K2_ + n] = __float2half(0.f);
        }
        return;
    }

    // ---------- MLP ----------
    uint32_t* W2t = smw;
    uint32_t* W3t = smw + H_*WSU;
    uint32_t* A   = smw + 2*H_*WSU;
    __shared__ float sW1[2*H_], sB1[H_], sB2[H_], sB3[H_], sW4[H_+1];

    const int w = tid >> 5, l = tid & 31;
    const int mrow = (w & 3) * 32, ncol = (w >> 2) * 64;

    for (int i = tid; i < H_*H_; i += 256){
        int k = i >> 7, n = i & 127;
        ((__half*)W2t)[n*(2*WSU) + k] = __float2half(W2[i]);
        ((__half*)W3t)[n*(2*WSU) + k] = __float2half(W3[i]);
    }
    if (tid < 2*H_) sW1[tid] = W1[tid];
    if (tid < H_){ sB1[tid] = b1[tid]; sB2[tid] = b2[tid]; sB3[tid] = b3[tid]; sW4[tid] = W4[tid]; }
    if (tid == 0) sW4[H_] = b4[0];
    __syncthreads();

    for (int t = 0; t < TPB; t++){
        const int p0 = (blockIdx.x * TPB + t) * 128;

        {
            const int p  = tid >> 1;
            const int jh = (tid & 1) * 64;
            float2 xy = ((const float2*)nodes)[p0 + p];
            #pragma unroll 8
            for (int j = jh; j < jh + 64; j += 2){
                float v0 = fast_tanh(fmaf(xy.x, sW1[j  ], fmaf(xy.y, sW1[H_+j  ], sB1[j  ])));
                float v1 = fast_tanh(fmaf(xy.x, sW1[j+1], fmaf(xy.y, sW1[H_+j+1], sB1[j+1])));
                A[p*WSU + (j >> 1)] = pkh(v0, v1);
            }
        }
        __syncthreads();

        mma_layer(A, W2t, sB2, l, mrow, ncol);
        mma_layer(A, W3t, sB3, l, mrow, ncol);

        if (tid < 128){
            const uint32_t* Af = A + tid*WSU;
            float acc = 0.f;
            #pragma unroll 8
            for (int k = 0; k < H_/2; k++){
                __half2 h = *(const __half2*)&Af[k];
                float2 f = __half22float2(h);
                acc = fmaf(f.x, sW4[2*k], acc);
                acc = fmaf(f.y, sW4[2*k+1], acc);
            }
            float ev = acc + sW4[H_];
            int p = p0 + tid;
            int e = p / NN_, n = p - e*NN_;
            float c00 = __ldg(&BDD[e*4 + 0]), c01 = __ldg(&BDD[e*4 + 1]);
            float c10 = __ldg(&BDD[e*4 + 2]), c11 = __ldg(&BDD[e*4 + 3]);
            g_evH[e*KP_ + n]       = __float2half((c00 + c10) * ev);
            g_evH[e*KP_ + NN_ + n] = __float2half((c01 + c11) * ev);
            if (n < KP_ - K2_) g_evH[e*KP_ + K2_ + n] = __float2half(0.f);
        }
        __syncthreads();
    }
}

// ============================================================
// Stage 2: fp16 mma 128m x 64n tiles; F prefetched via cp.async
// overlapping the MMA.
// ============================================================
__global__ __launch_bounds__(256, 3)
void gemm_loss(const float* __restrict__ J, const float* __restrict__ F,
               float* __restrict__ out){
    extern __shared__ __align__(16) uint32_t smg[];
    uint32_t* As = smg;                           // [128][GKU]
    uint32_t* Bs = smg + 128*GKU;                 // [64][GKU]
    float*    Js = (float*)(smg + 192*GKU);       // [128][NJ]
    float*    Fs = Js + 128*NJ;                   // [128][FS]
    const int tid = threadIdx.x;
    const int m0g = blockIdx.y * 128, n0g = blockIdx.x * 64;
    const int s0  = n0g / R_;

    const uint32_t sbase = (uint32_t)__cvta_generic_to_shared(smg);

    // group 0: As + Bs (needed before MMA)
    for (int idx = tid; idx < 128*10; idx += 256){
        int m = idx / 10, q = idx - m*10;
        cpa16(sbase + (m*GKU + q*4)*4, g_evH + (m0g + m)*KP_ + q*8);
    }
    for (int idx = tid; idx < 64*10; idx += 256){
        int n = idx / 10, q = idx - n*10;
        cpa16(sbase + (128*GKU + n*GKU + q*4)*4, g_AcatH + (n0g + n)*KP_ + q*8);
    }
    CPA_COMMIT();

    // group 1: F tile (only needed after MMA)
    const uint32_t fbase = sbase + (192*GKU + 128*NJ)*4;
    for (int idx = tid; idx < 128*16; idx += 256){
        int m = idx >> 4, q = idx & 15;
        cpa16(fbase + (m*FS + q*4)*4, F + (m0g + m)*SR_ + n0g + q*4);
    }
    CPA_COMMIT();

    // J slice (regular loads, small)
    for (int idx = tid; idx < 128*NJ; idx += 256){
        int m = idx / NJ, ss = idx - m*NJ;
        int s = s0 + ss;
        Js[idx] = (s < S_) ? -J[(m0g + m)*S_ + s] : 0.f;
    }

    CPA_WAIT1();          // As/Bs landed; F may still be in flight
    __syncthreads();

    const int w = tid >> 5, l = tid & 31;
    const int g = l >> 2, t = l & 3;
    const int mrow = (w & 3) * 32, ncol = (w >> 2) * 32;

    float c[2][4][4];
    #pragma unroll
    for (int mt = 0; mt < 2; mt++)
        #pragma unroll
        for (int nt = 0; nt < 4; nt++)
            #pragma unroll
            for (int i = 0; i < 4; i++) c[mt][nt][i] = 0.f;

    #pragma unroll
    for (int kk = 0; kk < 5; kk++){
        const int kw = kk * 8;
        uint32_t a[2][4];
        #pragma unroll
        for (int mt = 0; mt < 2; mt++){
            const int r = mrow + mt*16 + g;
            a[mt][0] = As[ r     *GKU + kw     + t];
            a[mt][1] = As[(r + 8)*GKU + kw     + t];
            a[mt][2] = As[ r     *GKU + kw + 4 + t];
            a[mt][3] = As[(r + 8)*GKU + kw + 4 + t];
        }
        #pragma unroll
        for (int nt = 0; nt < 4; nt++){
            const int n = ncol + nt*8 + g;
            uint32_t b[2];
            b[0] = Bs[n*GKU + kw     + t];
            b[1] = Bs[n*GKU + kw + 4 + t];
            hmma16(c[0][nt], a[0], b);
            hmma16(c[1][nt], a[1], b);
        }
    }

    CPA_WAIT0();          // F landed (overlapped with MMA above)
    __syncthreads();

    // fused epilogue from smem
    float lsum = 0.f;
    #pragma unroll
    for (int mt = 0; mt < 2; mt++){
        const int r0 = mrow + mt*16 + g;
        #pragma unroll
        for (int nt = 0; nt < 4; nt++){
            const int nl = ncol + nt*8 + 2*t;
            const int sA = (n0g + nl) / R_ - s0;
            const int sB = (n0g + nl + 1) / R_ - s0;
            float2 f0 = *(const float2*)&Fs[ r0      *FS + nl];
            float2 f1 = *(const float2*)&Fs[(r0 + 8) *FS + nl];
            float ja0 = Js[ r0      *NJ + sA], jb0 = Js[ r0      *NJ + sB];
            float ja1 = Js[(r0 + 8) *NJ + sA], jb1 = Js[(r0 + 8) *NJ + sB];
            float r00 = fmaf(ja0, c[mt][nt][0], -f0.x);
            float r01 = fmaf(jb0, c[mt][nt][1], -f0.y);
            float r10 = fmaf(ja1, c[mt][nt][2], -f1.x);
            float r11 = fmaf(jb1, c[mt][nt][3], -f1.y);
            lsum = fmaf(r00, r00, lsum);
            lsum = fmaf(r01, r01, lsum);
            lsum = fmaf(r10, r10, lsum);
            lsum = fmaf(r11, r11, lsum);
        }
    }

    __shared__ float red[256];
    red[tid] = lsum; __syncthreads();
    #pragma unroll
    for (int s = 128; s > 0; s >>= 1){
        if (tid < s) red[tid] += red[tid + s];
        __syncthreads();
    }

    __shared__ unsigned s_last;
    if (tid == 0){
        g_partial[blockIdx.y * GX + blockIdx.x] = red[0];
        __threadfence();
        unsigned t2 = atomicAdd(&g_count, 1u);
        s_last = (t2 == NPART - 1u) ? 1u : 0u;
    }
    __syncthreads();

    if (s_last){
        __shared__ double dred[256];
        double s = 0.0;
        for (int i = tid; i < NPART; i += 256) s += (double)g_partial[i];
        dred[tid] = s; __syncthreads();
        #pragma unroll
        for (int k = 128; k > 0; k >>= 1){
            if (tid < k) dred[tid] += dred[tid + k];
            __syncthreads();
        }
        if (tid == 0){
            out[0] = (float)(dred[0] / (double)R_);
            g_count = 0;
        }
    }
}

// ============================================================
extern "C" void kernel_launch(void* const* d_in, const int* in_sizes, int n_in,
                              void* d_out, int out_size){
    const float* nodes = (const float*)d_in[0];
    const float* W1    = (const float*)d_in[1];
    const float* b1    = (const float*)d_in[2];
    const float* W2    = (const float*)d_in[3];
    const float* b2    = (const float*)d_in[4];
    const float* W3    = (const float*)d_in[5];
    const float* b3    = (const float*)d_in[6];
    const float* W4    = (const float*)d_in[7];
    const float* b4    = (const float*)d_in[8];
    const float* Ixx   = (const float*)d_in[9];
    const float* Iyy   = (const float*)d_in[10];
    const float* BDD   = (const float*)d_in[11];
    const float* wq    = (const float*)d_in[12];
    const float* Base  = (const float*)d_in[13];
    const float* J     = (const float*)d_in[14];
    const float* F     = (const float*)d_in[15];

    const int s1_smem   = 3 * H_ * WSU * 4;                            // 104448 B
    const int gemm_smem = (192*GKU + 128*NJ + 128*FS) * 4;             // 71680 B
    cudaFuncSetAttribute(stage1,    cudaFuncAttributeMaxDynamicSharedMemorySize, s1_smem);
    cudaFuncSetAttribute(gemm_loss, cudaFuncAttributeMaxDynamicSharedMemorySize, gemm_smem);

    stage1<<<STAGE1_BLOCKS, 256, s1_smem>>>(nodes, W1, b1, W2, b2, W3, b3, W4, b4,
                                            BDD, Ixx, Iyy, wq, Base);
    gemm_loss<<<dim3(GX, GY), 256, gemm_smem>>>(J, F, (float*)d_out);
}